// round 5
// baseline (speedup 1.0000x reference)
#include <cuda_runtime.h>
#include <math.h>

typedef unsigned long long u64;

#define N_NODES 10000
#define N_EDGES 50000
#define NB      500
#define D       64
#define NODE_IN 15
#define EDGE_IN 5
#define EHID    128
#define DDIM    4096   // D*D
#define OUT_DIM 12
#define MP_STEPS 6
#define S2S_STEPS 6

// ---------------- scratch (device globals; no allocation allowed) ----------------
__device__ __align__(16) float g_We[(size_t)N_EDGES * DDIM];      // 819 MB
__device__ __align__(16) float g_hedge[N_EDGES * EHID];           // 25.6 MB
__device__ __align__(16) float g_h[N_NODES * D];                  // node state (out == GRU h)
__device__ __align__(16) float g_agg[N_NODES * D];
__device__ __align__(16) float g_e[N_NODES];
__device__            unsigned g_emax[NB];
__device__ __align__(16) float g_denom[NB];
__device__ __align__(16) float g_read[NB * D];
__device__ __align__(16) float g_qstar[NB * 2 * D];
__device__ __align__(16) float g_hl[3 * NB * D];
__device__ __align__(16) float g_cl[3 * NB * D];
__device__ __align__(16) float g_t1[NB * D];
// transposed weights for coalesced access
__device__ __align__(16) float g_WihT[D * 3 * D];        // [64][192]
__device__ __align__(16) float g_WhhT[D * 3 * D];
__device__ __align__(16) float g_L0ihT[2 * D * 4 * D];   // [128][256]
__device__ __align__(16) float g_L0hhT[D * 4 * D];       // [64][256]
__device__ __align__(16) float g_L12ihT[2 * D * 4 * D];  // 2 x [64][256]
__device__ __align__(16) float g_L12hhT[2 * D * 4 * D];

// ---------------- helpers ----------------
__device__ __forceinline__ void fma2(u64 &d, u64 a, u64 b) {
    asm("fma.rn.f32x2 %0, %1, %2, %0;" : "+l"(d) : "l"(a), "l"(b));
}
__device__ __forceinline__ u64 pack2(float x, float y) {
    u64 r; asm("mov.b64 %0, {%1, %2};" : "=l"(r) : "f"(x), "f"(y)); return r;
}
__device__ __forceinline__ float2 unpack2(u64 v) {
    float2 r; asm("mov.b64 {%0, %1}, %2;" : "=f"(r.x), "=f"(r.y) : "l"(v)); return r;
}
__device__ __forceinline__ float sigf(float x) { return 1.f / (1.f + expf(-x)); }
__device__ __forceinline__ unsigned f2o(float f) {
    unsigned u = __float_as_uint(f);
    return (u & 0x80000000u) ? ~u : (u | 0x80000000u);
}
__device__ __forceinline__ float o2f(unsigned o) {
    return (o & 0x80000000u) ? __uint_as_float(o & 0x7fffffffu) : __uint_as_float(~o);
}

// ---------------- prep: transpose small weight matrices ----------------
__global__ void k_prep(const float* __restrict__ gWih, const float* __restrict__ gWhh,
                       const float* __restrict__ l0ih, const float* __restrict__ l0hh,
                       const float* __restrict__ l12ih, const float* __restrict__ l12hh) {
    int tid = blockIdx.x * blockDim.x + threadIdx.x;
    int nt  = gridDim.x * blockDim.x;
    for (int x = tid; x < 192 * 64; x += nt) {
        int j = x / 64, i = x % 64;
        g_WihT[i * 192 + j] = gWih[j * 64 + i];
        g_WhhT[i * 192 + j] = gWhh[j * 64 + i];
    }
    for (int x = tid; x < 256 * 128; x += nt) {
        int j = x / 128, i = x % 128;
        g_L0ihT[i * 256 + j] = l0ih[j * 128 + i];
    }
    for (int x = tid; x < 256 * 64; x += nt) {
        int j = x / 64, i = x % 64;
        g_L0hhT[i * 256 + j] = l0hh[j * 64 + i];
    }
    for (int x = tid; x < 2 * 256 * 64; x += nt) {
        int l = x / 16384, rem = x % 16384;
        int j = rem / 64, i = rem % 64;
        g_L12ihT[l * 16384 + i * 256 + j] = l12ih[l * 16384 + j * 64 + i];
        g_L12hhT[l * 16384 + i * 256 + j] = l12hh[l * 16384 + j * 64 + i];
    }
}

// ---------------- lin0: out = relu(node_feat @ lin0_W + b) ----------------
__global__ void k_lin0(const float* __restrict__ nf, const float* __restrict__ W,
                       const float* __restrict__ b) {
    int idx = blockIdx.x * 256 + threadIdx.x;   // exactly N_NODES*64
    int n = idx >> 6, d = idx & 63;
    float acc = b[d];
#pragma unroll
    for (int i = 0; i < NODE_IN; i++) acc += nf[n * NODE_IN + i] * W[i * 64 + d];
    g_h[idx] = fmaxf(acc, 0.f);
}

// ---------------- edge hidden: h = relu(edge_feat @ W1 + b1) ----------------
__global__ void k_edgehid(const float* __restrict__ ef, const float* __restrict__ W1,
                          const float* __restrict__ b1) {
    int idx = blockIdx.x * 256 + threadIdx.x;   // exactly N_EDGES*128
    int e = idx >> 7, k = idx & 127;
    float acc = b1[k];
#pragma unroll
    for (int i = 0; i < EDGE_IN; i++) acc += ef[e * EDGE_IN + i] * W1[i * EHID + k];
    g_hedge[idx] = fmaxf(acc, 0.f);
}

// ---------------- big GEMM: We[E,4096] = g_hedge[E,128] @ W2[128,4096] + b2 ----------------
// 64x64 tile, K split into two 64-chunks, f32x2 packed FMA (FFMA2).
__global__ __launch_bounds__(256) void k_gemm(const float* __restrict__ W2,
                                              const float* __restrict__ b2) {
    __shared__ float As[64][68];
    __shared__ float Bs[64][68];
    const int tid = threadIdx.x;
    const int tx = tid & 15, ty = tid >> 4;
    const int e0 = blockIdx.y << 6;
    const int j0 = blockIdx.x << 6;
    u64 acc[4][2];
#pragma unroll
    for (int r = 0; r < 4; r++) { acc[r][0] = 0ull; acc[r][1] = 0ull; }

    for (int kb = 0; kb < 2; kb++) {
#pragma unroll
        for (int l = 0; l < 4; l++) {
            int idx = tid + l * 256;
            int r = idx >> 4, c4 = (idx & 15) << 2;
            float4 av = make_float4(0.f, 0.f, 0.f, 0.f);
            int e = e0 + r;
            if (e < N_EDGES)
                av = *(const float4*)(g_hedge + (size_t)e * 128 + kb * 64 + c4);
            *(float4*)&As[r][c4] = av;
            float4 bv = *(const float4*)(W2 + (size_t)(kb * 64 + r) * 4096 + j0 + c4);
            *(float4*)&Bs[r][c4] = bv;
        }
        __syncthreads();
#pragma unroll 8
        for (int k = 0; k < 64; k++) {
            u64 b0 = *(const u64*)&Bs[k][tx * 4];
            u64 b1 = *(const u64*)&Bs[k][tx * 4 + 2];
#pragma unroll
            for (int r = 0; r < 4; r++) {
                float a = As[ty * 4 + r][k];
                u64 pa = pack2(a, a);
                fma2(acc[r][0], pa, b0);
                fma2(acc[r][1], pa, b1);
            }
        }
        __syncthreads();
    }
    float4 bv = *(const float4*)(b2 + j0 + (tx << 2));
#pragma unroll
    for (int r = 0; r < 4; r++) {
        int e = e0 + ty * 4 + r;
        if (e >= N_EDGES) break;
        float2 p0 = unpack2(acc[r][0]);
        float2 p1 = unpack2(acc[r][1]);
        float4 o = make_float4(p0.x + bv.x, p0.y + bv.y, p1.x + bv.z, p1.y + bv.w);
        *(float4*)(g_We + (size_t)e * 4096 + j0 + (tx << 2)) = o;
    }
}

// ---------------- per-step: agg = conv_bias (then scatter-add) ----------------
__global__ void k_initagg(const float* __restrict__ cb) {
    int idx = blockIdx.x * 256 + threadIdx.x;   // exactly N_NODES*64
    g_agg[idx] = cb[idx & 63];
}

// ---------------- einsum + scatter: warp per edge, HBM-bound over We ----------------
__global__ void k_einsum(const int* __restrict__ src, const int* __restrict__ dst) {
    __shared__ float xs[8][64];
    int w = threadIdx.x >> 5, t = threadIdx.x & 31;
    int e = (blockIdx.x << 3) + w;              // exactly N_EDGES
    int s = src[e];
    int j = t << 1;
    float2 v = *(const float2*)(g_h + s * 64 + j);
    xs[w][j] = v.x; xs[w][j + 1] = v.y;
    __syncwarp();
    const u64* __restrict__ Wr = (const u64*)(g_We + (size_t)e * 4096);
    u64 acc = 0ull;
#pragma unroll 4
    for (int i = 0; i < 64; i++) {
        float xi = xs[w][i];
        fma2(acc, pack2(xi, xi), Wr[i * 32 + t]);
    }
    float2 m = unpack2(acc);
    int dn = dst[e];
    atomicAdd(g_agg + dn * 64 + j, m.x);
    atomicAdd(g_agg + dn * 64 + j + 1, m.y);
}

// ---------------- GRU cell: warp per node, f32x2, transposed weights ----------------
__global__ void k_gru(const float* __restrict__ bih, const float* __restrict__ bhh) {
    __shared__ float sm[4][64];
    __shared__ float sh[4][64];
    int w = threadIdx.x >> 5, t = threadIdx.x & 31;
    int n = (blockIdx.x << 2) + w;              // exactly N_NODES
    int j = t << 1;
    float2 av = *(const float2*)(g_agg + n * 64 + j);
    sm[w][j] = fmaxf(av.x, 0.f); sm[w][j + 1] = fmaxf(av.y, 0.f);
    float2 hv = *(const float2*)(g_h + n * 64 + j);
    sh[w][j] = hv.x; sh[w][j + 1] = hv.y;
    __syncwarp();
    const u64* __restrict__ WX = (const u64*)g_WihT;
    const u64* __restrict__ WH = (const u64*)g_WhhT;
    u64 arx = 0, azx = 0, anx = 0, arh = 0, azh = 0, anh = 0;
#pragma unroll 4
    for (int i = 0; i < 64; i++) {
        float xi = sm[w][i], hi = sh[w][i];
        u64 px = pack2(xi, xi), ph = pack2(hi, hi);
        int base = i * 96 + t;                  // u64 index into [64][192]
        fma2(arx, px, WX[base]);
        fma2(azx, px, WX[base + 32]);
        fma2(anx, px, WX[base + 64]);
        fma2(arh, ph, WH[base]);
        fma2(azh, ph, WH[base + 32]);
        fma2(anh, ph, WH[base + 64]);
    }
    float2 rx = unpack2(arx), zx = unpack2(azx), nx = unpack2(anx);
    float2 rh = unpack2(arh), zh = unpack2(azh), nh = unpack2(anh);
    float r0 = sigf(rx.x + bih[j]       + rh.x + bhh[j]);
    float r1 = sigf(rx.y + bih[j + 1]   + rh.y + bhh[j + 1]);
    float z0 = sigf(zx.x + bih[64 + j]  + zh.x + bhh[64 + j]);
    float z1 = sigf(zx.y + bih[64 + j+1]+ zh.y + bhh[64 + j + 1]);
    float n0 = tanhf(nx.x + bih[128 + j]     + r0 * (nh.x + bhh[128 + j]));
    float n1 = tanhf(nx.y + bih[128 + j + 1] + r1 * (nh.y + bhh[128 + j + 1]));
    float2 o;
    o.x = (1.f - z0) * n0 + z0 * hv.x;
    o.y = (1.f - z1) * n1 + z1 * hv.y;
    *(float2*)(g_h + n * 64 + j) = o;
}

// ---------------- Set2Set ----------------
__global__ void k_s2sinit() {
    int idx = blockIdx.x * 256 + threadIdx.x;   // exactly 3*NB*64 = 96000
    g_hl[idx] = 0.f;
    g_cl[idx] = 0.f;
    if (idx < NB * 2 * D) g_qstar[idx] = 0.f;
}

__global__ void k_lstm(int layer, const float* __restrict__ bih, const float* __restrict__ bhh) {
    __shared__ float xs[2 * D];
    __shared__ float hs[D];
    int b = blockIdx.x, d = threadIdx.x;
    const float* x; const float* WT; const float* UT; int in_dim;
    if (layer == 0) { x = g_qstar + b * 128; WT = g_L0ihT; UT = g_L0hhT; in_dim = 128; }
    else {
        x = g_hl + (layer - 1) * NB * D + b * 64;
        WT = g_L12ihT + (layer - 1) * 64 * 256;
        UT = g_L12hhT + (layer - 1) * 64 * 256;
        in_dim = 64;
    }
    float* h = g_hl + layer * NB * D;
    float* c = g_cl + layer * NB * D;
    for (int i = d; i < in_dim; i += 64) xs[i] = x[i];
    hs[d] = h[b * 64 + d];
    __syncthreads();
    float gi = bih[d] + bhh[d];
    float gf = bih[64 + d] + bhh[64 + d];
    float gg = bih[128 + d] + bhh[128 + d];
    float go = bih[192 + d] + bhh[192 + d];
#pragma unroll 4
    for (int i = 0; i < in_dim; i++) {
        float xi = xs[i];
        const float* wr = WT + i * 256;
        gi += xi * wr[d]; gf += xi * wr[64 + d]; gg += xi * wr[128 + d]; go += xi * wr[192 + d];
    }
#pragma unroll 4
    for (int i = 0; i < 64; i++) {
        float hi = hs[i];
        const float* wr = UT + i * 256;
        gi += hi * wr[d]; gf += hi * wr[64 + d]; gg += hi * wr[128 + d]; go += hi * wr[192 + d];
    }
    float cc = sigf(gf) * c[b * 64 + d] + sigf(gi) * tanhf(gg);
    float hh = sigf(go) * tanhf(cc);
    c[b * 64 + d] = cc;
    h[b * 64 + d] = hh;
}

__global__ void k_attinit() {
    int idx = blockIdx.x * 256 + threadIdx.x;
    if (idx < NB) g_emax[idx] = 0u;                               // == "-inf" in ordered space
    else if (idx < 2 * NB) g_denom[idx - NB] = 0.f;
    else if (idx < 2 * NB + NB * D) g_read[idx - 2 * NB] = 0.f;
}

__global__ void k_atte(const int* __restrict__ gid) {
    int w = threadIdx.x >> 5, t = threadIdx.x & 31;
    int n = (blockIdx.x << 3) + w;              // exactly N_NODES
    int g = gid[n];
    const float* q = g_hl + 2 * NB * D;
    int j = t << 1;
    float2 ov = *(const float2*)(g_h + n * 64 + j);
    float2 qv = *(const float2*)(q + g * 64 + j);
    float s = ov.x * qv.x + ov.y * qv.y;
#pragma unroll
    for (int o = 16; o; o >>= 1) s += __shfl_xor_sync(0xffffffffu, s, o);
    if (t == 0) {
        g_e[n] = s;
        atomicMax(&g_emax[g], f2o(s));
    }
}

__global__ void k_attexp(const int* __restrict__ gid) {
    int n = blockIdx.x * 256 + threadIdx.x;
    if (n >= N_NODES) return;
    int g = gid[n];
    float m = o2f(g_emax[g]);
    float ex = expf(g_e[n] - m);
    g_e[n] = ex;
    atomicAdd(&g_denom[g], ex);
}

__global__ void k_attread(const int* __restrict__ gid) {
    int w = threadIdx.x >> 5, t = threadIdx.x & 31;
    int n = (blockIdx.x << 3) + w;              // exactly N_NODES
    int g = gid[n];
    float alpha = g_e[n] / g_denom[g];
    int j = t << 1;
    float2 ov = *(const float2*)(g_h + n * 64 + j);
    atomicAdd(g_read + g * 64 + j, alpha * ov.x);
    atomicAdd(g_read + g * 64 + j + 1, alpha * ov.y);
}

__global__ void k_qstar() {
    int idx = blockIdx.x * 256 + threadIdx.x;   // exactly NB*128
    int b = idx >> 7, j = idx & 127;
    const float* q = g_hl + 2 * NB * D;
    g_qstar[idx] = (j < 64) ? q[b * 64 + j] : g_read[b * 64 + (j - 64)];
}

// ---------------- output head ----------------
__global__ void k_head1(const float* __restrict__ W, const float* __restrict__ b) {
    int idx = blockIdx.x * 256 + threadIdx.x;   // exactly NB*64
    int bb = idx >> 6, d = idx & 63;
    float acc = b[d];
#pragma unroll 4
    for (int i = 0; i < 128; i++) acc += g_qstar[bb * 128 + i] * W[i * 64 + d];
    g_t1[idx] = fmaxf(acc, 0.f);
}

__global__ void k_head2(const float* __restrict__ W, const float* __restrict__ b,
                        float* __restrict__ out) {
    int idx = blockIdx.x * 256 + threadIdx.x;
    if (idx >= NB * OUT_DIM) return;
    int bb = idx / OUT_DIM, o = idx % OUT_DIM;
    float acc = b[o];
#pragma unroll 4
    for (int d = 0; d < 64; d++) acc += g_t1[bb * 64 + d] * W[d * OUT_DIM + o];
    out[idx] = acc;
}

// ---------------- launcher ----------------
extern "C" void kernel_launch(void* const* d_in, const int* in_sizes, int n_in,
                              void* d_out, int out_size) {
    const float* node_feat = (const float*)d_in[0];
    const float* edge_feat = (const float*)d_in[1];
    const int*   src       = (const int*)d_in[2];
    const int*   dst       = (const int*)d_in[3];
    const int*   gid       = (const int*)d_in[4];
    // d_in[5] = num_graphs (unused; B fixed)
    const float* lin0_W = (const float*)d_in[6];
    const float* lin0_b = (const float*)d_in[7];
    const float* em_W1  = (const float*)d_in[8];
    const float* em_b1  = (const float*)d_in[9];
    const float* em_W2  = (const float*)d_in[10];
    const float* em_b2  = (const float*)d_in[11];
    const float* conv_bias = (const float*)d_in[12];
    const float* gru_Wih = (const float*)d_in[13];
    const float* gru_Whh = (const float*)d_in[14];
    const float* gru_bih = (const float*)d_in[15];
    const float* gru_bhh = (const float*)d_in[16];
    const float* l0_Wih = (const float*)d_in[17];
    const float* l0_Whh = (const float*)d_in[18];
    const float* l0_bih = (const float*)d_in[19];
    const float* l0_bhh = (const float*)d_in[20];
    const float* l12_Wih = (const float*)d_in[21];
    const float* l12_Whh = (const float*)d_in[22];
    const float* l12_bih = (const float*)d_in[23];
    const float* l12_bhh = (const float*)d_in[24];
    const float* lin1_W = (const float*)d_in[25];
    const float* lin1_b = (const float*)d_in[26];
    const float* lin2_W = (const float*)d_in[27];
    const float* lin2_b = (const float*)d_in[28];
    float* out = (float*)d_out;

    (void)in_sizes; (void)n_in; (void)out_size;

    k_prep<<<128, 256>>>(gru_Wih, gru_Whh, l0_Wih, l0_Whh, l12_Wih, l12_Whh);
    k_lin0<<<(N_NODES * 64) / 256, 256>>>(node_feat, lin0_W, lin0_b);
    k_edgehid<<<(N_EDGES * EHID) / 256, 256>>>(edge_feat, em_W1, em_b1);
    k_gemm<<<dim3(DDIM / 64, (N_EDGES + 63) / 64), 256>>>(em_W2, em_b2);

    for (int s = 0; s < MP_STEPS; s++) {
        k_initagg<<<(N_NODES * 64) / 256, 256>>>(conv_bias);
        k_einsum<<<N_EDGES / 8, 256>>>(src, dst);
        k_gru<<<N_NODES / 4, 128>>>(gru_bih, gru_bhh);
    }

    k_s2sinit<<<(3 * NB * D) / 256, 256>>>();
    for (int s = 0; s < S2S_STEPS; s++) {
        k_lstm<<<NB, 64>>>(0, l0_bih, l0_bhh);
        k_lstm<<<NB, 64>>>(1, l12_bih, l12_bhh);
        k_lstm<<<NB, 64>>>(2, l12_bih + 256, l12_bhh + 256);
        k_attinit<<<(2 * NB + NB * D + 255) / 256, 256>>>();
        k_atte<<<N_NODES / 8, 256>>>(gid);
        k_attexp<<<(N_NODES + 255) / 256, 256>>>(gid);
        k_attread<<<N_NODES / 8, 256>>>(gid);
        k_qstar<<<(NB * 128) / 256, 256>>>();
    }

    k_head1<<<(NB * 64) / 256, 256>>>(lin1_W, lin1_b);
    k_head2<<<(NB * OUT_DIM + 255) / 256, 256>>>(lin2_W, lin2_b, out);
}

// round 6
// speedup vs baseline: 1.1442x; 1.1442x over previous
#include <cuda_runtime.h>
#include <cuda_fp16.h>
#include <math.h>

typedef unsigned long long u64;

#define N_NODES 10000
#define N_EDGES 50000
#define NB      500
#define D       64
#define NODE_IN 15
#define EDGE_IN 5
#define EHID    128
#define DDIM    4096   // D*D
#define OUT_DIM 12
#define MP_STEPS 6
#define S2S_STEPS 6

// ---------------- scratch (device globals; no allocation allowed) ----------------
__device__ __align__(16) __half g_We16[(size_t)N_EDGES * DDIM]; // 410 MB fp16
__device__ __align__(16) float g_hedge[N_EDGES * EHID];         // 25.6 MB
__device__ __align__(16) float g_h[N_NODES * D];                // node state (out == GRU h)
__device__ __align__(16) float g_agg[N_NODES * D];
__device__ __align__(16) float g_e[N_NODES];
__device__            unsigned g_emax[NB];
__device__ __align__(16) float g_denom[NB];
__device__ __align__(16) float g_read[NB * D];
__device__ __align__(16) float g_qstar[NB * 2 * D];
__device__ __align__(16) float g_hl[3 * NB * D];
__device__ __align__(16) float g_cl[3 * NB * D];
__device__ __align__(16) float g_t1[NB * D];
// transposed weights for coalesced access
__device__ __align__(16) float g_WihT[D * 3 * D];        // [64][192]
__device__ __align__(16) float g_WhhT[D * 3 * D];
__device__ __align__(16) float g_L0ihT[2 * D * 4 * D];   // [128][256]
__device__ __align__(16) float g_L0hhT[D * 4 * D];       // [64][256]
__device__ __align__(16) float g_L12ihT[2 * D * 4 * D];  // 2 x [64][256]
__device__ __align__(16) float g_L12hhT[2 * D * 4 * D];

// ---------------- helpers ----------------
__device__ __forceinline__ void fma2(u64 &d, u64 a, u64 b) {
    asm("fma.rn.f32x2 %0, %1, %2, %0;" : "+l"(d) : "l"(a), "l"(b));
}
__device__ __forceinline__ u64 pack2(float x, float y) {
    u64 r; asm("mov.b64 %0, {%1, %2};" : "=l"(r) : "f"(x), "f"(y)); return r;
}
__device__ __forceinline__ float2 unpack2(u64 v) {
    float2 r; asm("mov.b64 {%0, %1}, %2;" : "=f"(r.x), "=f"(r.y) : "l"(v)); return r;
}
__device__ __forceinline__ float sigf(float x) { return 1.f / (1.f + expf(-x)); }
__device__ __forceinline__ unsigned f2o(float f) {
    unsigned u = __float_as_uint(f);
    return (u & 0x80000000u) ? ~u : (u | 0x80000000u);
}
__device__ __forceinline__ float o2f(unsigned o) {
    return (o & 0x80000000u) ? __uint_as_float(o & 0x7fffffffu) : __uint_as_float(~o);
}

// ---------------- prep: transpose small weight matrices ----------------
__global__ void k_prep(const float* __restrict__ gWih, const float* __restrict__ gWhh,
                       const float* __restrict__ l0ih, const float* __restrict__ l0hh,
                       const float* __restrict__ l12ih, const float* __restrict__ l12hh) {
    int tid = blockIdx.x * blockDim.x + threadIdx.x;
    int nt  = gridDim.x * blockDim.x;
    for (int x = tid; x < 192 * 64; x += nt) {
        int j = x / 64, i = x % 64;
        g_WihT[i * 192 + j] = gWih[j * 64 + i];
        g_WhhT[i * 192 + j] = gWhh[j * 64 + i];
    }
    for (int x = tid; x < 256 * 128; x += nt) {
        int j = x / 128, i = x % 128;
        g_L0ihT[i * 256 + j] = l0ih[j * 128 + i];
    }
    for (int x = tid; x < 256 * 64; x += nt) {
        int j = x / 64, i = x % 64;
        g_L0hhT[i * 256 + j] = l0hh[j * 64 + i];
    }
    for (int x = tid; x < 2 * 256 * 64; x += nt) {
        int l = x / 16384, rem = x % 16384;
        int j = rem / 64, i = rem % 64;
        g_L12ihT[l * 16384 + i * 256 + j] = l12ih[l * 16384 + j * 64 + i];
        g_L12hhT[l * 16384 + i * 256 + j] = l12hh[l * 16384 + j * 64 + i];
    }
}

// ---------------- lin0: out = relu(node_feat @ lin0_W + b) ----------------
__global__ void k_lin0(const float* __restrict__ nf, const float* __restrict__ W,
                       const float* __restrict__ b) {
    int idx = blockIdx.x * 256 + threadIdx.x;   // exactly N_NODES*64
    int n = idx >> 6, d = idx & 63;
    float acc = b[d];
#pragma unroll
    for (int i = 0; i < NODE_IN; i++) acc += nf[n * NODE_IN + i] * W[i * 64 + d];
    g_h[idx] = fmaxf(acc, 0.f);
}

// ---------------- edge hidden: h = relu(edge_feat @ W1 + b1) ----------------
__global__ void k_edgehid(const float* __restrict__ ef, const float* __restrict__ W1,
                          const float* __restrict__ b1) {
    int idx = blockIdx.x * 256 + threadIdx.x;   // exactly N_EDGES*128
    int e = idx >> 7, k = idx & 127;
    float acc = b1[k];
#pragma unroll
    for (int i = 0; i < EDGE_IN; i++) acc += ef[e * EDGE_IN + i] * W1[i * EHID + k];
    g_hedge[idx] = fmaxf(acc, 0.f);
}

// ---------------- big GEMM: We16[E,4096] = fp16(g_hedge[E,128] @ W2[128,4096] + b2) ---------
// Tile 128(M) x 64(N), K-chunks of 32. A stored transposed in smem so LDS.128 yields
// packed M-pairs directly (no packing MOVs for A; broadcast across tx on the crossbar).
// Each thread: 8M x 4N via 16 FFMA2 per k.
__global__ __launch_bounds__(256) void k_gemm(const float* __restrict__ W2,
                                              const float* __restrict__ b2) {
    __shared__ float As[32][136];   // [k][m], padded
    __shared__ float Bs[32][68];    // [k][n], padded
    const int tid = threadIdx.x;
    const int tx = tid & 15, ty = tid >> 4;
    const int e0 = blockIdx.y << 7;       // 128 edge rows
    const int j0 = blockIdx.x << 6;       // 64 output cols
    u64 acc[4][4];
#pragma unroll
    for (int mp = 0; mp < 4; mp++)
#pragma unroll
        for (int n = 0; n < 4; n++) acc[mp][n] = 0ull;

    const int c8 = tid >> 5;   // 0..7  (k-group of 4)
    const int mb = tid & 31;   // m base (distinct across warp -> conflict-free STS)

    for (int kb = 0; kb < 4; kb++) {
        // A fill (transposed): 128 m x 32 k
#pragma unroll
        for (int l = 0; l < 4; l++) {
            int m = mb + l * 32;
            int e = e0 + m;
            float4 av = make_float4(0.f, 0.f, 0.f, 0.f);
            if (e < N_EDGES)
                av = *(const float4*)(g_hedge + (size_t)e * 128 + kb * 32 + c8 * 4);
            As[c8 * 4 + 0][m] = av.x;
            As[c8 * 4 + 1][m] = av.y;
            As[c8 * 4 + 2][m] = av.z;
            As[c8 * 4 + 3][m] = av.w;
        }
        // B fill: 32 k x 64 n
#pragma unroll
        for (int l = 0; l < 2; l++) {
            int idx = tid + l * 256;
            int r = idx >> 4, c4 = (idx & 15) << 2;
            *(float4*)&Bs[r][c4] = *(const float4*)(W2 + (size_t)(kb * 32 + r) * 4096 + j0 + c4);
        }
        __syncthreads();
#pragma unroll
        for (int k = 0; k < 32; k++) {
            float4 a0 = *(const float4*)&As[k][ty * 8];
            float4 a1 = *(const float4*)&As[k][ty * 8 + 4];
            float4 b  = *(const float4*)&Bs[k][tx * 4];
            u64 ap0 = pack2(a0.x, a0.y), ap1 = pack2(a0.z, a0.w);
            u64 ap2 = pack2(a1.x, a1.y), ap3 = pack2(a1.z, a1.w);
            u64 bb0 = pack2(b.x, b.x), bb1 = pack2(b.y, b.y);
            u64 bb2 = pack2(b.z, b.z), bb3 = pack2(b.w, b.w);
            fma2(acc[0][0], ap0, bb0); fma2(acc[0][1], ap0, bb1);
            fma2(acc[0][2], ap0, bb2); fma2(acc[0][3], ap0, bb3);
            fma2(acc[1][0], ap1, bb0); fma2(acc[1][1], ap1, bb1);
            fma2(acc[1][2], ap1, bb2); fma2(acc[1][3], ap1, bb3);
            fma2(acc[2][0], ap2, bb0); fma2(acc[2][1], ap2, bb1);
            fma2(acc[2][2], ap2, bb2); fma2(acc[2][3], ap2, bb3);
            fma2(acc[3][0], ap3, bb0); fma2(acc[3][1], ap3, bb1);
            fma2(acc[3][2], ap3, bb2); fma2(acc[3][3], ap3, bb3);
        }
        __syncthreads();
    }
    // epilogue: add bias, convert to fp16, 8B coalesced stores
    float4 bv = *(const float4*)(b2 + j0 + (tx << 2));
#pragma unroll
    for (int mp = 0; mp < 4; mp++) {
        float2 c0 = unpack2(acc[mp][0]);
        float2 c1 = unpack2(acc[mp][1]);
        float2 c2 = unpack2(acc[mp][2]);
        float2 c3 = unpack2(acc[mp][3]);
        int m0 = ty * 8 + mp * 2;
        int e_a = e0 + m0;
        if (e_a < N_EDGES) {
            __half2 p0 = __floats2half2_rn(c0.x + bv.x, c1.x + bv.y);
            __half2 p1 = __floats2half2_rn(c2.x + bv.z, c3.x + bv.w);
            uint2 v; v.x = *(unsigned*)&p0; v.y = *(unsigned*)&p1;
            *(uint2*)(g_We16 + (size_t)e_a * 4096 + j0 + (tx << 2)) = v;
        }
        int e_b = e_a + 1;
        if (e_b < N_EDGES) {
            __half2 p0 = __floats2half2_rn(c0.y + bv.x, c1.y + bv.y);
            __half2 p1 = __floats2half2_rn(c2.y + bv.z, c3.y + bv.w);
            uint2 v; v.x = *(unsigned*)&p0; v.y = *(unsigned*)&p1;
            *(uint2*)(g_We16 + (size_t)e_b * 4096 + j0 + (tx << 2)) = v;
        }
    }
}

// ---------------- per-step: agg = conv_bias (then scatter-add) ----------------
__global__ void k_initagg(const float* __restrict__ cb) {
    int idx = blockIdx.x * 256 + threadIdx.x;   // exactly N_NODES*64
    g_agg[idx] = cb[idx & 63];
}

// ---------------- einsum + scatter: warp per edge, HBM-bound over fp16 We ----------------
__global__ void k_einsum(const int* __restrict__ src, const int* __restrict__ dst) {
    __shared__ float xs[8][64];
    int w = threadIdx.x >> 5, t = threadIdx.x & 31;
    int e = (blockIdx.x << 3) + w;              // exactly N_EDGES
    int s = src[e];
    int j = t << 1;
    float2 v = *(const float2*)(g_h + s * 64 + j);
    xs[w][j] = v.x; xs[w][j + 1] = v.y;
    __syncwarp();
    const __half2* __restrict__ Wr = (const __half2*)(g_We16 + (size_t)e * 4096);
    float ax = 0.f, ay = 0.f;
#pragma unroll 8
    for (int i = 0; i < 64; i++) {
        float xi = xs[w][i];
        float2 wf = __half22float2(Wr[i * 32 + t]);
        ax = fmaf(xi, wf.x, ax);
        ay = fmaf(xi, wf.y, ay);
    }
    int dn = dst[e];
    atomicAdd(g_agg + dn * 64 + j, ax);
    atomicAdd(g_agg + dn * 64 + j + 1, ay);
}

// ---------------- GRU cell: warp per node, f32x2, transposed weights ----------------
__global__ void k_gru(const float* __restrict__ bih, const float* __restrict__ bhh) {
    __shared__ float sm[4][64];
    __shared__ float sh[4][64];
    int w = threadIdx.x >> 5, t = threadIdx.x & 31;
    int n = (blockIdx.x << 2) + w;              // exactly N_NODES
    int j = t << 1;
    float2 av = *(const float2*)(g_agg + n * 64 + j);
    sm[w][j] = fmaxf(av.x, 0.f); sm[w][j + 1] = fmaxf(av.y, 0.f);
    float2 hv = *(const float2*)(g_h + n * 64 + j);
    sh[w][j] = hv.x; sh[w][j + 1] = hv.y;
    __syncwarp();
    const u64* __restrict__ WX = (const u64*)g_WihT;
    const u64* __restrict__ WH = (const u64*)g_WhhT;
    u64 arx = 0, azx = 0, anx = 0, arh = 0, azh = 0, anh = 0;
#pragma unroll 4
    for (int i = 0; i < 64; i++) {
        float xi = sm[w][i], hi = sh[w][i];
        u64 px = pack2(xi, xi), ph = pack2(hi, hi);
        int base = i * 96 + t;                  // u64 index into [64][192]
        fma2(arx, px, WX[base]);
        fma2(azx, px, WX[base + 32]);
        fma2(anx, px, WX[base + 64]);
        fma2(arh, ph, WH[base]);
        fma2(azh, ph, WH[base + 32]);
        fma2(anh, ph, WH[base + 64]);
    }
    float2 rx = unpack2(arx), zx = unpack2(azx), nx = unpack2(anx);
    float2 rh = unpack2(arh), zh = unpack2(azh), nh = unpack2(anh);
    float r0 = sigf(rx.x + bih[j]       + rh.x + bhh[j]);
    float r1 = sigf(rx.y + bih[j + 1]   + rh.y + bhh[j + 1]);
    float z0 = sigf(zx.x + bih[64 + j]  + zh.x + bhh[64 + j]);
    float z1 = sigf(zx.y + bih[64 + j+1]+ zh.y + bhh[64 + j + 1]);
    float n0 = tanhf(nx.x + bih[128 + j]     + r0 * (nh.x + bhh[128 + j]));
    float n1 = tanhf(nx.y + bih[128 + j + 1] + r1 * (nh.y + bhh[128 + j + 1]));
    float2 o;
    o.x = (1.f - z0) * n0 + z0 * hv.x;
    o.y = (1.f - z1) * n1 + z1 * hv.y;
    *(float2*)(g_h + n * 64 + j) = o;
}

// ---------------- Set2Set ----------------
__global__ void k_s2sinit() {
    int idx = blockIdx.x * 256 + threadIdx.x;   // exactly 3*NB*64 = 96000
    g_hl[idx] = 0.f;
    g_cl[idx] = 0.f;
    if (idx < NB * 2 * D) g_qstar[idx] = 0.f;
}

__global__ void k_lstm(int layer, const float* __restrict__ bih, const float* __restrict__ bhh) {
    __shared__ float xs[2 * D];
    __shared__ float hs[D];
    int b = blockIdx.x, d = threadIdx.x;
    const float* x; const float* WT; const float* UT; int in_dim;
    if (layer == 0) { x = g_qstar + b * 128; WT = g_L0ihT; UT = g_L0hhT; in_dim = 128; }
    else {
        x = g_hl + (layer - 1) * NB * D + b * 64;
        WT = g_L12ihT + (layer - 1) * 64 * 256;
        UT = g_L12hhT + (layer - 1) * 64 * 256;
        in_dim = 64;
    }
    float* h = g_hl + layer * NB * D;
    float* c = g_cl + layer * NB * D;
    for (int i = d; i < in_dim; i += 64) xs[i] = x[i];
    hs[d] = h[b * 64 + d];
    __syncthreads();
    float gi = bih[d] + bhh[d];
    float gf = bih[64 + d] + bhh[64 + d];
    float gg = bih[128 + d] + bhh[128 + d];
    float go = bih[192 + d] + bhh[192 + d];
#pragma unroll 4
    for (int i = 0; i < in_dim; i++) {
        float xi = xs[i];
        const float* wr = WT + i * 256;
        gi += xi * wr[d]; gf += xi * wr[64 + d]; gg += xi * wr[128 + d]; go += xi * wr[192 + d];
    }
#pragma unroll 4
    for (int i = 0; i < 64; i++) {
        float hi = hs[i];
        const float* wr = UT + i * 256;
        gi += hi * wr[d]; gf += hi * wr[64 + d]; gg += hi * wr[128 + d]; go += hi * wr[192 + d];
    }
    float cc = sigf(gf) * c[b * 64 + d] + sigf(gi) * tanhf(gg);
    float hh = sigf(go) * tanhf(cc);
    c[b * 64 + d] = cc;
    h[b * 64 + d] = hh;
}

__global__ void k_attinit() {
    int idx = blockIdx.x * 256 + threadIdx.x;
    if (idx < NB) g_emax[idx] = 0u;                               // == "-inf" in ordered space
    else if (idx < 2 * NB) g_denom[idx - NB] = 0.f;
    else if (idx < 2 * NB + NB * D) g_read[idx - 2 * NB] = 0.f;
}

__global__ void k_atte(const int* __restrict__ gid) {
    int w = threadIdx.x >> 5, t = threadIdx.x & 31;
    int n = (blockIdx.x << 3) + w;              // exactly N_NODES
    int g = gid[n];
    const float* q = g_hl + 2 * NB * D;
    int j = t << 1;
    float2 ov = *(const float2*)(g_h + n * 64 + j);
    float2 qv = *(const float2*)(q + g * 64 + j);
    float s = ov.x * qv.x + ov.y * qv.y;
#pragma unroll
    for (int o = 16; o; o >>= 1) s += __shfl_xor_sync(0xffffffffu, s, o);
    if (t == 0) {
        g_e[n] = s;
        atomicMax(&g_emax[g], f2o(s));
    }
}

__global__ void k_attexp(const int* __restrict__ gid) {
    int n = blockIdx.x * 256 + threadIdx.x;
    if (n >= N_NODES) return;
    int g = gid[n];
    float m = o2f(g_emax[g]);
    float ex = expf(g_e[n] - m);
    g_e[n] = ex;
    atomicAdd(&g_denom[g], ex);
}

__global__ void k_attread(const int* __restrict__ gid) {
    int w = threadIdx.x >> 5, t = threadIdx.x & 31;
    int n = (blockIdx.x << 3) + w;              // exactly N_NODES
    int g = gid[n];
    float alpha = g_e[n] / g_denom[g];
    int j = t << 1;
    float2 ov = *(const float2*)(g_h + n * 64 + j);
    atomicAdd(g_read + g * 64 + j, alpha * ov.x);
    atomicAdd(g_read + g * 64 + j + 1, alpha * ov.y);
}

__global__ void k_qstar() {
    int idx = blockIdx.x * 256 + threadIdx.x;   // exactly NB*128
    int b = idx >> 7, j = idx & 127;
    const float* q = g_hl + 2 * NB * D;
    g_qstar[idx] = (j < 64) ? q[b * 64 + j] : g_read[b * 64 + (j - 64)];
}

// ---------------- output head ----------------
__global__ void k_head1(const float* __restrict__ W, const float* __restrict__ b) {
    int idx = blockIdx.x * 256 + threadIdx.x;   // exactly NB*64
    int bb = idx >> 6, d = idx & 63;
    float acc = b[d];
#pragma unroll 4
    for (int i = 0; i < 128; i++) acc += g_qstar[bb * 128 + i] * W[i * 64 + d];
    g_t1[idx] = fmaxf(acc, 0.f);
}

__global__ void k_head2(const float* __restrict__ W, const float* __restrict__ b,
                        float* __restrict__ out) {
    int idx = blockIdx.x * 256 + threadIdx.x;
    if (idx >= NB * OUT_DIM) return;
    int bb = idx / OUT_DIM, o = idx % OUT_DIM;
    float acc = b[o];
#pragma unroll 4
    for (int d = 0; d < 64; d++) acc += g_t1[bb * 64 + d] * W[d * OUT_DIM + o];
    out[idx] = acc;
}

// ---------------- launcher ----------------
extern "C" void kernel_launch(void* const* d_in, const int* in_sizes, int n_in,
                              void* d_out, int out_size) {
    const float* node_feat = (const float*)d_in[0];
    const float* edge_feat = (const float*)d_in[1];
    const int*   src       = (const int*)d_in[2];
    const int*   dst       = (const int*)d_in[3];
    const int*   gid       = (const int*)d_in[4];
    // d_in[5] = num_graphs (unused; B fixed)
    const float* lin0_W = (const float*)d_in[6];
    const float* lin0_b = (const float*)d_in[7];
    const float* em_W1  = (const float*)d_in[8];
    const float* em_b1  = (const float*)d_in[9];
    const float* em_W2  = (const float*)d_in[10];
    const float* em_b2  = (const float*)d_in[11];
    const float* conv_bias = (const float*)d_in[12];
    const float* gru_Wih = (const float*)d_in[13];
    const float* gru_Whh = (const float*)d_in[14];
    const float* gru_bih = (const float*)d_in[15];
    const float* gru_bhh = (const float*)d_in[16];
    const float* l0_Wih = (const float*)d_in[17];
    const float* l0_Whh = (const float*)d_in[18];
    const float* l0_bih = (const float*)d_in[19];
    const float* l0_bhh = (const float*)d_in[20];
    const float* l12_Wih = (const float*)d_in[21];
    const float* l12_Whh = (const float*)d_in[22];
    const float* l12_bih = (const float*)d_in[23];
    const float* l12_bhh = (const float*)d_in[24];
    const float* lin1_W = (const float*)d_in[25];
    const float* lin1_b = (const float*)d_in[26];
    const float* lin2_W = (const float*)d_in[27];
    const float* lin2_b = (const float*)d_in[28];
    float* out = (float*)d_out;

    (void)in_sizes; (void)n_in; (void)out_size;

    k_prep<<<128, 256>>>(gru_Wih, gru_Whh, l0_Wih, l0_Whh, l12_Wih, l12_Whh);
    k_lin0<<<(N_NODES * 64) / 256, 256>>>(node_feat, lin0_W, lin0_b);
    k_edgehid<<<(N_EDGES * EHID) / 256, 256>>>(edge_feat, em_W1, em_b1);
    k_gemm<<<dim3(DDIM / 64, (N_EDGES + 127) / 128), 256>>>(em_W2, em_b2);

    for (int s = 0; s < MP_STEPS; s++) {
        k_initagg<<<(N_NODES * 64) / 256, 256>>>(conv_bias);
        k_einsum<<<N_EDGES / 8, 256>>>(src, dst);
        k_gru<<<N_NODES / 4, 128>>>(gru_bih, gru_bhh);
    }

    k_s2sinit<<<(3 * NB * D) / 256, 256>>>();
    for (int s = 0; s < S2S_STEPS; s++) {
        k_lstm<<<NB, 64>>>(0, l0_bih, l0_bhh);
        k_lstm<<<NB, 64>>>(1, l12_bih, l12_bhh);
        k_lstm<<<NB, 64>>>(2, l12_bih + 256, l12_bhh + 256);
        k_attinit<<<(2 * NB + NB * D + 255) / 256, 256>>>();
        k_atte<<<N_NODES / 8, 256>>>(gid);
        k_attexp<<<(N_NODES + 255) / 256, 256>>>(gid);
        k_attread<<<N_NODES / 8, 256>>>(gid);
        k_qstar<<<(NB * 128) / 256, 256>>>();
    }

    k_head1<<<(NB * 64) / 256, 256>>>(lin1_W, lin1_b);
    k_head2<<<(NB * OUT_DIM + 255) / 256, 256>>>(lin2_W, lin2_b, out);
}

// round 7
// speedup vs baseline: 1.8409x; 1.6088x over previous
#include <cuda_runtime.h>
#include <cuda_fp16.h>
#include <math.h>

typedef unsigned long long u64;

#define N_NODES 10000
#define N_EDGES 50000
#define NB      500
#define D       64
#define NODE_IN 15
#define EDGE_IN 5
#define EHID    128
#define DDIM    4096   // D*D
#define OUT_DIM 12
#define MP_STEPS 6
#define S2S_STEPS 6

// ---------------- scratch (device globals; no allocation allowed) ----------------
__device__ __align__(16) __half g_We16[(size_t)N_EDGES * DDIM]; // 410 MB fp16
__device__ __align__(16) __half g_hedge16[N_EDGES * EHID];      // 12.8 MB fp16
__device__ __align__(16) __half g_W2h[EHID * DDIM];             // 1 MB fp16
__device__ __align__(16) float g_h[N_NODES * D];                // node state
__device__ __align__(16) float g_agg[N_NODES * D];
__device__ __align__(16) float g_e[N_NODES];
__device__            unsigned g_emax[NB];
__device__ __align__(16) float g_denom[NB];
__device__ __align__(16) float g_read[NB * D];
__device__ __align__(16) float g_qstar[NB * 2 * D];
__device__ __align__(16) float g_hl[3 * NB * D];
__device__ __align__(16) float g_cl[3 * NB * D];
__device__ __align__(16) float g_t1[NB * D];
// transposed weights for coalesced access
__device__ __align__(16) float g_WihT[D * 3 * D];        // [64][192]
__device__ __align__(16) float g_WhhT[D * 3 * D];
__device__ __align__(16) float g_L0ihT[2 * D * 4 * D];   // [128][256]
__device__ __align__(16) float g_L0hhT[D * 4 * D];       // [64][256]
__device__ __align__(16) float g_L12ihT[2 * D * 4 * D];  // 2 x [64][256]
__device__ __align__(16) float g_L12hhT[2 * D * 4 * D];

// ---------------- helpers ----------------
__device__ __forceinline__ void fma2(u64 &d, u64 a, u64 b) {
    asm("fma.rn.f32x2 %0, %1, %2, %0;" : "+l"(d) : "l"(a), "l"(b));
}
__device__ __forceinline__ u64 pack2(float x, float y) {
    u64 r; asm("mov.b64 %0, {%1, %2};" : "=l"(r) : "f"(x), "f"(y)); return r;
}
__device__ __forceinline__ float2 unpack2(u64 v) {
    float2 r; asm("mov.b64 {%0, %1}, %2;" : "=f"(r.x), "=f"(r.y) : "l"(v)); return r;
}
__device__ __forceinline__ float sigf(float x) { return 1.f / (1.f + expf(-x)); }
__device__ __forceinline__ unsigned f2o(float f) {
    unsigned u = __float_as_uint(f);
    return (u & 0x80000000u) ? ~u : (u | 0x80000000u);
}
__device__ __forceinline__ float o2f(unsigned o) {
    return (o & 0x80000000u) ? __uint_as_float(o & 0x7fffffffu) : __uint_as_float(~o);
}
__device__ __forceinline__ unsigned sm_u32(const void* p) {
    return (unsigned)__cvta_generic_to_shared(p);
}
#define LDSM4(r0,r1,r2,r3,addr) \
    asm volatile("ldmatrix.sync.aligned.m8n8.x4.shared.b16 {%0,%1,%2,%3}, [%4];" \
        : "=r"(r0),"=r"(r1),"=r"(r2),"=r"(r3) : "r"(addr))
#define LDSM4T(r0,r1,r2,r3,addr) \
    asm volatile("ldmatrix.sync.aligned.m8n8.x4.trans.shared.b16 {%0,%1,%2,%3}, [%4];" \
        : "=r"(r0),"=r"(r1),"=r"(r2),"=r"(r3) : "r"(addr))
#define MMA16816(d,a,b0,b1) \
    asm volatile("mma.sync.aligned.m16n8k16.row.col.f32.f16.f16.f32 " \
        "{%0,%1,%2,%3}, {%4,%5,%6,%7}, {%8,%9}, {%0,%1,%2,%3};" \
        : "+f"((d)[0]),"+f"((d)[1]),"+f"((d)[2]),"+f"((d)[3]) \
        : "r"((a)[0]),"r"((a)[1]),"r"((a)[2]),"r"((a)[3]), "r"(b0),"r"(b1))

// ---------------- prep: transpose small weight matrices + fp16 W2 ----------------
__global__ void k_prep(const float* __restrict__ gWih, const float* __restrict__ gWhh,
                       const float* __restrict__ l0ih, const float* __restrict__ l0hh,
                       const float* __restrict__ l12ih, const float* __restrict__ l12hh,
                       const float* __restrict__ W2) {
    int tid = blockIdx.x * blockDim.x + threadIdx.x;
    int nt  = gridDim.x * blockDim.x;
    for (int x = tid; x < 192 * 64; x += nt) {
        int j = x / 64, i = x % 64;
        g_WihT[i * 192 + j] = gWih[j * 64 + i];
        g_WhhT[i * 192 + j] = gWhh[j * 64 + i];
    }
    for (int x = tid; x < 256 * 128; x += nt) {
        int j = x / 128, i = x % 128;
        g_L0ihT[i * 256 + j] = l0ih[j * 128 + i];
    }
    for (int x = tid; x < 256 * 64; x += nt) {
        int j = x / 64, i = x % 64;
        g_L0hhT[i * 256 + j] = l0hh[j * 64 + i];
    }
    for (int x = tid; x < 2 * 256 * 64; x += nt) {
        int l = x / 16384, rem = x % 16384;
        int j = rem / 64, i = rem % 64;
        g_L12ihT[l * 16384 + i * 256 + j] = l12ih[l * 16384 + j * 64 + i];
        g_L12hhT[l * 16384 + i * 256 + j] = l12hh[l * 16384 + j * 64 + i];
    }
    for (int x = tid; x < EHID * DDIM; x += nt)
        g_W2h[x] = __float2half(W2[x]);
}

// ---------------- lin0: out = relu(node_feat @ lin0_W + b) ----------------
__global__ void k_lin0(const float* __restrict__ nf, const float* __restrict__ W,
                       const float* __restrict__ b) {
    int idx = blockIdx.x * 256 + threadIdx.x;   // exactly N_NODES*64
    int n = idx >> 6, d = idx & 63;
    float acc = b[d];
#pragma unroll
    for (int i = 0; i < NODE_IN; i++) acc += nf[n * NODE_IN + i] * W[i * 64 + d];
    g_h[idx] = fmaxf(acc, 0.f);
}

// ---------------- edge hidden (fp16 out): h = relu(edge_feat @ W1 + b1) ----------------
__global__ void k_edgehid(const float* __restrict__ ef, const float* __restrict__ W1,
                          const float* __restrict__ b1) {
    int idx = blockIdx.x * 256 + threadIdx.x;   // exactly N_EDGES*128
    int e = idx >> 7, k = idx & 127;
    float acc = b1[k];
#pragma unroll
    for (int i = 0; i < EDGE_IN; i++) acc += ef[e * EDGE_IN + i] * W1[i * EHID + k];
    g_hedge16[idx] = __float2half(fmaxf(acc, 0.f));
}

// ---------------- big GEMM via HMMA: We16 = fp16(hedge16 @ W2h + b2) ----------------
// Block tile 128(M) x 128(N), K-chunks of 32. 8 warps as 2(M) x 4(N); warp tile 64x32.
// ldmatrix + xor-swizzled smem, mma.sync.m16n8k16 with fp32 accum.
#define BM 128
#define BN 128
#define BK 32
__global__ __launch_bounds__(256, 2) void k_gemm(const float* __restrict__ b2) {
    __shared__ __half As[BM * BK];   // 8 KB, chunk-swizzled
    __shared__ __half Bs[BK * BN];   // 8 KB, chunk-swizzled
    const int tid = threadIdx.x;
    const int wid = tid >> 5, lane = tid & 31;
    const int warp_m = wid & 1, warp_n = wid >> 1;
    const int e0 = blockIdx.y * BM;
    const int j0 = blockIdx.x * BN;
    const int li = lane & 7, grp = lane >> 3;
    const unsigned As_b = sm_u32(As), Bs_b = sm_u32(Bs);

    float acc[4][4][4];
#pragma unroll
    for (int f = 0; f < 4; f++)
#pragma unroll
        for (int j = 0; j < 4; j++)
#pragma unroll
            for (int q = 0; q < 4; q++) acc[f][j][q] = 0.f;

    for (int kb = 0; kb < 4; kb++) {
        // A fill: 128 rows x 32 k (fp16), 512 chunks of 16B, swizzle ck ^= row&3
#pragma unroll
        for (int l = 0; l < 2; l++) {
            int cid = tid + l * 256;
            int row = cid >> 2, ck = cid & 3;
            uint4 v = make_uint4(0u, 0u, 0u, 0u);
            int e = e0 + row;
            if (e < N_EDGES)
                v = *(const uint4*)(g_hedge16 + (size_t)e * 128 + kb * 32 + ck * 8);
            *(uint4*)(As + ((row << 2) + (ck ^ (row & 3))) * 8) = v;
        }
        // B fill: 32 rows x 128 n, 512 chunks, swizzle ck ^= row&7
#pragma unroll
        for (int l = 0; l < 2; l++) {
            int cid = tid + l * 256;
            int row = cid >> 4, ck = cid & 15;
            uint4 v = *(const uint4*)(g_W2h + (size_t)(kb * 32 + row) * 4096 + j0 + ck * 8);
            *(uint4*)(Bs + ((row << 4) + (ck ^ (row & 7))) * 8) = v;
        }
        __syncthreads();
#pragma unroll
        for (int s = 0; s < 2; s++) {
            unsigned a[4][4];
#pragma unroll
            for (int f = 0; f < 4; f++) {
                int m0 = warp_m * 64 + f * 16;
                int row = m0 + li + (grp & 1) * 8;
                int ck = (s * 2 + (grp >> 1)) ^ (row & 3);
                LDSM4(a[f][0], a[f][1], a[f][2], a[f][3],
                      As_b + ((row << 2) + ck) * 16);
            }
            unsigned b[2][4];
#pragma unroll
            for (int p = 0; p < 2; p++) {
                int n0 = warp_n * 32 + p * 16;
                int row = s * 16 + li + (grp & 1) * 8;
                int ck = ((n0 >> 3) + (grp >> 1)) ^ (row & 7);
                LDSM4T(b[p][0], b[p][1], b[p][2], b[p][3],
                       Bs_b + ((row << 4) + ck) * 16);
            }
#pragma unroll
            for (int f = 0; f < 4; f++) {
                MMA16816(acc[f][0], a[f], b[0][0], b[0][1]);
                MMA16816(acc[f][1], a[f], b[0][2], b[0][3]);
                MMA16816(acc[f][2], a[f], b[1][0], b[1][1]);
                MMA16816(acc[f][3], a[f], b[1][2], b[1][3]);
            }
        }
        __syncthreads();
    }
    // epilogue: + bias, fp16, direct 4B stores
#pragma unroll
    for (int j = 0; j < 4; j++) {
        int cn = warp_n * 32 + j * 8 + (lane & 3) * 2;
        float bv0 = b2[j0 + cn], bv1 = b2[j0 + cn + 1];
#pragma unroll
        for (int f = 0; f < 4; f++) {
            int r = warp_m * 64 + f * 16 + (lane >> 2);
            int e = e0 + r;
            if (e < N_EDGES) {
                __half2 h = __floats2half2_rn(acc[f][j][0] + bv0, acc[f][j][1] + bv1);
                *(__half2*)(g_We16 + (size_t)e * 4096 + j0 + cn) = h;
            }
            if (e + 8 < N_EDGES) {
                __half2 h = __floats2half2_rn(acc[f][j][2] + bv0, acc[f][j][3] + bv1);
                *(__half2*)(g_We16 + (size_t)(e + 8) * 4096 + j0 + cn) = h;
            }
        }
    }
}

// ---------------- per-step: agg = conv_bias (then scatter-add) ----------------
__global__ void k_initagg(const float* __restrict__ cb) {
    int idx = blockIdx.x * 256 + threadIdx.x;   // exactly N_NODES*64
    g_agg[idx] = cb[idx & 63];
}

// ---------------- einsum + scatter: warp per edge, HBM-bound over fp16 We ----------------
__global__ void k_einsum(const int* __restrict__ src, const int* __restrict__ dst) {
    __shared__ float xs[8][64];
    int w = threadIdx.x >> 5, t = threadIdx.x & 31;
    int e = (blockIdx.x << 3) + w;              // exactly N_EDGES
    int s = src[e];
    int j = t << 1;
    float2 v = *(const float2*)(g_h + s * 64 + j);
    xs[w][j] = v.x; xs[w][j + 1] = v.y;
    __syncwarp();
    const __half2* __restrict__ Wr = (const __half2*)(g_We16 + (size_t)e * 4096);
    float ax = 0.f, ay = 0.f;
#pragma unroll 8
    for (int i = 0; i < 64; i++) {
        float xi = xs[w][i];
        float2 wf = __half22float2(Wr[i * 32 + t]);
        ax = fmaf(xi, wf.x, ax);
        ay = fmaf(xi, wf.y, ay);
    }
    int dn = dst[e];
    atomicAdd(g_agg + dn * 64 + j, ax);
    atomicAdd(g_agg + dn * 64 + j + 1, ay);
}

// ---------------- GRU cell: warp per node, f32x2, transposed weights ----------------
__global__ void k_gru(const float* __restrict__ bih, const float* __restrict__ bhh) {
    __shared__ float sm[4][64];
    __shared__ float sh[4][64];
    int w = threadIdx.x >> 5, t = threadIdx.x & 31;
    int n = (blockIdx.x << 2) + w;              // exactly N_NODES
    int j = t << 1;
    float2 av = *(const float2*)(g_agg + n * 64 + j);
    sm[w][j] = fmaxf(av.x, 0.f); sm[w][j + 1] = fmaxf(av.y, 0.f);
    float2 hv = *(const float2*)(g_h + n * 64 + j);
    sh[w][j] = hv.x; sh[w][j + 1] = hv.y;
    __syncwarp();
    const u64* __restrict__ WX = (const u64*)g_WihT;
    const u64* __restrict__ WH = (const u64*)g_WhhT;
    u64 arx = 0, azx = 0, anx = 0, arh = 0, azh = 0, anh = 0;
#pragma unroll 4
    for (int i = 0; i < 64; i++) {
        float xi = sm[w][i], hi = sh[w][i];
        u64 px = pack2(xi, xi), ph = pack2(hi, hi);
        int base = i * 96 + t;                  // u64 index into [64][192]
        fma2(arx, px, WX[base]);
        fma2(azx, px, WX[base + 32]);
        fma2(anx, px, WX[base + 64]);
        fma2(arh, ph, WH[base]);
        fma2(azh, ph, WH[base + 32]);
        fma2(anh, ph, WH[base + 64]);
    }
    float2 rx = unpack2(arx), zx = unpack2(azx), nx = unpack2(anx);
    float2 rh = unpack2(arh), zh = unpack2(azh), nh = unpack2(anh);
    float r0 = sigf(rx.x + bih[j]       + rh.x + bhh[j]);
    float r1 = sigf(rx.y + bih[j + 1]   + rh.y + bhh[j + 1]);
    float z0 = sigf(zx.x + bih[64 + j]  + zh.x + bhh[64 + j]);
    float z1 = sigf(zx.y + bih[64 + j+1]+ zh.y + bhh[64 + j + 1]);
    float n0 = tanhf(nx.x + bih[128 + j]     + r0 * (nh.x + bhh[128 + j]));
    float n1 = tanhf(nx.y + bih[128 + j + 1] + r1 * (nh.y + bhh[128 + j + 1]));
    float2 o;
    o.x = (1.f - z0) * n0 + z0 * hv.x;
    o.y = (1.f - z1) * n1 + z1 * hv.y;
    *(float2*)(g_h + n * 64 + j) = o;
}

// ---------------- Set2Set ----------------
__global__ void k_s2sinit() {
    int idx = blockIdx.x * 256 + threadIdx.x;   // exactly 3*NB*64 = 96000
    g_hl[idx] = 0.f;
    g_cl[idx] = 0.f;
    if (idx < NB * 2 * D) g_qstar[idx] = 0.f;
}

__global__ void k_lstm(int layer, const float* __restrict__ bih, const float* __restrict__ bhh) {
    __shared__ float xs[2 * D];
    __shared__ float hs[D];
    int b = blockIdx.x, d = threadIdx.x;
    const float* x; const float* WT; const float* UT; int in_dim;
    if (layer == 0) { x = g_qstar + b * 128; WT = g_L0ihT; UT = g_L0hhT; in_dim = 128; }
    else {
        x = g_hl + (layer - 1) * NB * D + b * 64;
        WT = g_L12ihT + (layer - 1) * 64 * 256;
        UT = g_L12hhT + (layer - 1) * 64 * 256;
        in_dim = 64;
    }
    float* h = g_hl + layer * NB * D;
    float* c = g_cl + layer * NB * D;
    for (int i = d; i < in_dim; i += 64) xs[i] = x[i];
    hs[d] = h[b * 64 + d];
    __syncthreads();
    float gi = bih[d] + bhh[d];
    float gf = bih[64 + d] + bhh[64 + d];
    float gg = bih[128 + d] + bhh[128 + d];
    float go = bih[192 + d] + bhh[192 + d];
#pragma unroll 4
    for (int i = 0; i < in_dim; i++) {
        float xi = xs[i];
        const float* wr = WT + i * 256;
        gi += xi * wr[d]; gf += xi * wr[64 + d]; gg += xi * wr[128 + d]; go += xi * wr[192 + d];
    }
#pragma unroll 4
    for (int i = 0; i < 64; i++) {
        float hi = hs[i];
        const float* wr = UT + i * 256;
        gi += hi * wr[d]; gf += hi * wr[64 + d]; gg += hi * wr[128 + d]; go += hi * wr[192 + d];
    }
    float cc = sigf(gf) * c[b * 64 + d] + sigf(gi) * tanhf(gg);
    float hh = sigf(go) * tanhf(cc);
    c[b * 64 + d] = cc;
    h[b * 64 + d] = hh;
}

__global__ void k_attinit() {
    int idx = blockIdx.x * 256 + threadIdx.x;
    if (idx < NB) g_emax[idx] = 0u;                               // == "-inf" in ordered space
    else if (idx < 2 * NB) g_denom[idx - NB] = 0.f;
    else if (idx < 2 * NB + NB * D) g_read[idx - 2 * NB] = 0.f;
}

__global__ void k_atte(const int* __restrict__ gid) {
    int w = threadIdx.x >> 5, t = threadIdx.x & 31;
    int n = (blockIdx.x << 3) + w;              // exactly N_NODES
    int g = gid[n];
    const float* q = g_hl + 2 * NB * D;
    int j = t << 1;
    float2 ov = *(const float2*)(g_h + n * 64 + j);
    float2 qv = *(const float2*)(q + g * 64 + j);
    float s = ov.x * qv.x + ov.y * qv.y;
#pragma unroll
    for (int o = 16; o; o >>= 1) s += __shfl_xor_sync(0xffffffffu, s, o);
    if (t == 0) {
        g_e[n] = s;
        atomicMax(&g_emax[g], f2o(s));
    }
}

__global__ void k_attexp(const int* __restrict__ gid) {
    int n = blockIdx.x * 256 + threadIdx.x;
    if (n >= N_NODES) return;
    int g = gid[n];
    float m = o2f(g_emax[g]);
    float ex = expf(g_e[n] - m);
    g_e[n] = ex;
    atomicAdd(&g_denom[g], ex);
}

__global__ void k_attread(const int* __restrict__ gid) {
    int w = threadIdx.x >> 5, t = threadIdx.x & 31;
    int n = (blockIdx.x << 3) + w;              // exactly N_NODES
    int g = gid[n];
    float alpha = g_e[n] / g_denom[g];
    int j = t << 1;
    float2 ov = *(const float2*)(g_h + n * 64 + j);
    atomicAdd(g_read + g * 64 + j, alpha * ov.x);
    atomicAdd(g_read + g * 64 + j + 1, alpha * ov.y);
}

__global__ void k_qstar() {
    int idx = blockIdx.x * 256 + threadIdx.x;   // exactly NB*128
    int b = idx >> 7, j = idx & 127;
    const float* q = g_hl + 2 * NB * D;
    g_qstar[idx] = (j < 64) ? q[b * 64 + j] : g_read[b * 64 + (j - 64)];
}

// ---------------- output head ----------------
__global__ void k_head1(const float* __restrict__ W, const float* __restrict__ b) {
    int idx = blockIdx.x * 256 + threadIdx.x;   // exactly NB*64
    int bb = idx >> 6, d = idx & 63;
    float acc = b[d];
#pragma unroll 4
    for (int i = 0; i < 128; i++) acc += g_qstar[bb * 128 + i] * W[i * 64 + d];
    g_t1[idx] = fmaxf(acc, 0.f);
}

__global__ void k_head2(const float* __restrict__ W, const float* __restrict__ b,
                        float* __restrict__ out) {
    int idx = blockIdx.x * 256 + threadIdx.x;
    if (idx >= NB * OUT_DIM) return;
    int bb = idx / OUT_DIM, o = idx % OUT_DIM;
    float acc = b[o];
#pragma unroll 4
    for (int d = 0; d < 64; d++) acc += g_t1[bb * 64 + d] * W[d * OUT_DIM + o];
    out[idx] = acc;
}

// ---------------- launcher ----------------
extern "C" void kernel_launch(void* const* d_in, const int* in_sizes, int n_in,
                              void* d_out, int out_size) {
    const float* node_feat = (const float*)d_in[0];
    const float* edge_feat = (const float*)d_in[1];
    const int*   src       = (const int*)d_in[2];
    const int*   dst       = (const int*)d_in[3];
    const int*   gid       = (const int*)d_in[4];
    // d_in[5] = num_graphs (unused; B fixed)
    const float* lin0_W = (const float*)d_in[6];
    const float* lin0_b = (const float*)d_in[7];
    const float* em_W1  = (const float*)d_in[8];
    const float* em_b1  = (const float*)d_in[9];
    const float* em_W2  = (const float*)d_in[10];
    const float* em_b2  = (const float*)d_in[11];
    const float* conv_bias = (const float*)d_in[12];
    const float* gru_Wih = (const float*)d_in[13];
    const float* gru_Whh = (const float*)d_in[14];
    const float* gru_bih = (const float*)d_in[15];
    const float* gru_bhh = (const float*)d_in[16];
    const float* l0_Wih = (const float*)d_in[17];
    const float* l0_Whh = (const float*)d_in[18];
    const float* l0_bih = (const float*)d_in[19];
    const float* l0_bhh = (const float*)d_in[20];
    const float* l12_Wih = (const float*)d_in[21];
    const float* l12_Whh = (const float*)d_in[22];
    const float* l12_bih = (const float*)d_in[23];
    const float* l12_bhh = (const float*)d_in[24];
    const float* lin1_W = (const float*)d_in[25];
    const float* lin1_b = (const float*)d_in[26];
    const float* lin2_W = (const float*)d_in[27];
    const float* lin2_b = (const float*)d_in[28];
    float* out = (float*)d_out;

    (void)in_sizes; (void)n_in; (void)out_size;

    k_prep<<<128, 256>>>(gru_Wih, gru_Whh, l0_Wih, l0_Whh, l12_Wih, l12_Whh, em_W2);
    k_lin0<<<(N_NODES * 64) / 256, 256>>>(node_feat, lin0_W, lin0_b);
    k_edgehid<<<(N_EDGES * EHID) / 256, 256>>>(edge_feat, em_W1, em_b1);
    k_gemm<<<dim3(DDIM / BN, (N_EDGES + BM - 1) / BM), 256>>>(em_b2);

    for (int s = 0; s < MP_STEPS; s++) {
        k_initagg<<<(N_NODES * 64) / 256, 256>>>(conv_bias);
        k_einsum<<<N_EDGES / 8, 256>>>(src, dst);
        k_gru<<<N_NODES / 4, 128>>>(gru_bih, gru_bhh);
    }

    k_s2sinit<<<(3 * NB * D) / 256, 256>>>();
    for (int s = 0; s < S2S_STEPS; s++) {
        k_lstm<<<NB, 64>>>(0, l0_bih, l0_bhh);
        k_lstm<<<NB, 64>>>(1, l12_bih, l12_bhh);
        k_lstm<<<NB, 64>>>(2, l12_bih + 256, l12_bhh + 256);
        k_attinit<<<(2 * NB + NB * D + 255) / 256, 256>>>();
        k_atte<<<N_NODES / 8, 256>>>(gid);
        k_attexp<<<(N_NODES + 255) / 256, 256>>>(gid);
        k_attread<<<N_NODES / 8, 256>>>(gid);
        k_qstar<<<(NB * 128) / 256, 256>>>();
    }

    k_head1<<<(NB * 64) / 256, 256>>>(lin1_W, lin1_b);
    k_head2<<<(NB * OUT_DIM + 255) / 256, 256>>>(lin2_W, lin2_b, out);
}

// round 9
// speedup vs baseline: 2.3127x; 1.2563x over previous
#include <cuda_runtime.h>
#include <cuda_fp16.h>
#include <math.h>

typedef unsigned long long u64;

#define N_NODES 10000
#define N_EDGES 50000
#define NB      500
#define D       64
#define NODE_IN 15
#define EDGE_IN 5
#define EHID    128
#define DDIM    4096   // D*D
#define OUT_DIM 12
#define MP_STEPS 6
#define S2S_STEPS 6

// ---------------- scratch (device globals; no allocation allowed) ----------------
__device__ __align__(16) __half g_We16[(size_t)N_EDGES * DDIM]; // 410 MB fp16
__device__ __align__(16) __half g_hedge16[N_EDGES * EHID];      // 12.8 MB fp16
__device__ __align__(16) __half g_W2h[EHID * DDIM];             // 1 MB fp16
__device__ __align__(16) float g_h[N_NODES * D];                // node state
__device__ __align__(16) float g_agg[N_NODES * D];
// GRU weights (fp32, transposed)
__device__ __align__(16) float g_WihT[D * 3 * D];        // [64][192]
__device__ __align__(16) float g_WhhT[D * 3 * D];
// LSTM weights (fp16, transposed: [in][256])
__device__ __align__(16) __half g_L0ihT[2 * D * 4 * D];  // [128][256]
__device__ __align__(16) __half g_L0hhT[D * 4 * D];      // [64][256]
__device__ __align__(16) __half g_L12ihT[2 * D * 4 * D]; // 2 x [64][256]
__device__ __align__(16) __half g_L12hhT[2 * D * 4 * D];

// ---------------- helpers ----------------
__device__ __forceinline__ void fma2(u64 &d, u64 a, u64 b) {
    asm("fma.rn.f32x2 %0, %1, %2, %0;" : "+l"(d) : "l"(a), "l"(b));
}
__device__ __forceinline__ u64 pack2(float x, float y) {
    u64 r; asm("mov.b64 %0, {%1, %2};" : "=l"(r) : "f"(x), "f"(y)); return r;
}
__device__ __forceinline__ float2 unpack2(u64 v) {
    float2 r; asm("mov.b64 {%0, %1}, %2;" : "=f"(r.x), "=f"(r.y) : "l"(v)); return r;
}
__device__ __forceinline__ float sigf(float x) { return 1.f / (1.f + expf(-x)); }
__device__ __forceinline__ unsigned sm_u32(const void* p) {
    return (unsigned)__cvta_generic_to_shared(p);
}
#define LDSM4(r0,r1,r2,r3,addr) \
    asm volatile("ldmatrix.sync.aligned.m8n8.x4.shared.b16 {%0,%1,%2,%3}, [%4];" \
        : "=r"(r0),"=r"(r1),"=r"(r2),"=r"(r3) : "r"(addr))
#define LDSM4T(r0,r1,r2,r3,addr) \
    asm volatile("ldmatrix.sync.aligned.m8n8.x4.trans.shared.b16 {%0,%1,%2,%3}, [%4];" \
        : "=r"(r0),"=r"(r1),"=r"(r2),"=r"(r3) : "r"(addr))
#define MMA16816(d,a,b0,b1) \
    asm volatile("mma.sync.aligned.m16n8k16.row.col.f32.f16.f16.f32 " \
        "{%0,%1,%2,%3}, {%4,%5,%6,%7}, {%8,%9}, {%0,%1,%2,%3};" \
        : "+f"((d)[0]),"+f"((d)[1]),"+f"((d)[2]),"+f"((d)[3]) \
        : "r"((a)[0]),"r"((a)[1]),"r"((a)[2]),"r"((a)[3]), "r"(b0),"r"(b1))

// ---------------- prep: transpose small weight matrices + fp16 conversions ---------------
__global__ void k_prep(const float* __restrict__ gWih, const float* __restrict__ gWhh,
                       const float* __restrict__ l0ih, const float* __restrict__ l0hh,
                       const float* __restrict__ l12ih, const float* __restrict__ l12hh,
                       const float* __restrict__ W2) {
    int tid = blockIdx.x * blockDim.x + threadIdx.x;
    int nt  = gridDim.x * blockDim.x;
    for (int x = tid; x < 192 * 64; x += nt) {
        int j = x / 64, i = x % 64;
        g_WihT[i * 192 + j] = gWih[j * 64 + i];
        g_WhhT[i * 192 + j] = gWhh[j * 64 + i];
    }
    for (int x = tid; x < 256 * 128; x += nt) {
        int j = x / 128, i = x % 128;
        g_L0ihT[i * 256 + j] = __float2half(l0ih[j * 128 + i]);
    }
    for (int x = tid; x < 256 * 64; x += nt) {
        int j = x / 64, i = x % 64;
        g_L0hhT[i * 256 + j] = __float2half(l0hh[j * 64 + i]);
    }
    for (int x = tid; x < 2 * 256 * 64; x += nt) {
        int l = x / 16384, rem = x % 16384;
        int j = rem / 64, i = rem % 64;
        g_L12ihT[l * 16384 + i * 256 + j] = __float2half(l12ih[l * 16384 + j * 64 + i]);
        g_L12hhT[l * 16384 + i * 256 + j] = __float2half(l12hh[l * 16384 + j * 64 + i]);
    }
    for (int x = tid; x < EHID * DDIM; x += nt)
        g_W2h[x] = __float2half(W2[x]);
}

// ---------------- lin0: out = relu(node_feat @ lin0_W + b) ----------------
__global__ void k_lin0(const float* __restrict__ nf, const float* __restrict__ W,
                       const float* __restrict__ b) {
    int idx = blockIdx.x * 256 + threadIdx.x;   // exactly N_NODES*64
    int n = idx >> 6, d = idx & 63;
    float acc = b[d];
#pragma unroll
    for (int i = 0; i < NODE_IN; i++) acc += nf[n * NODE_IN + i] * W[i * 64 + d];
    g_h[idx] = fmaxf(acc, 0.f);
}

// ---------------- edge hidden (fp16 out): h = relu(edge_feat @ W1 + b1) ----------------
__global__ void k_edgehid(const float* __restrict__ ef, const float* __restrict__ W1,
                          const float* __restrict__ b1) {
    int idx = blockIdx.x * 256 + threadIdx.x;   // exactly N_EDGES*128
    int e = idx >> 7, k = idx & 127;
    float acc = b1[k];
#pragma unroll
    for (int i = 0; i < EDGE_IN; i++) acc += ef[e * EDGE_IN + i] * W1[i * EHID + k];
    g_hedge16[idx] = __float2half(fmaxf(acc, 0.f));
}

// ---------------- big GEMM via HMMA: We16 = fp16(hedge16 @ W2h + b2) ----------------
#define BM 128
#define BN 128
#define BK 32
__global__ __launch_bounds__(256, 2) void k_gemm(const float* __restrict__ b2) {
    __shared__ __half As[BM * BK];   // 8 KB, chunk-swizzled
    __shared__ __half Bs[BK * BN];   // 8 KB, chunk-swizzled
    const int tid = threadIdx.x;
    const int wid = tid >> 5, lane = tid & 31;
    const int warp_m = wid & 1, warp_n = wid >> 1;
    const int e0 = blockIdx.y * BM;
    const int j0 = blockIdx.x * BN;
    const int li = lane & 7, grp = lane >> 3;
    const unsigned As_b = sm_u32(As), Bs_b = sm_u32(Bs);

    float acc[4][4][4];
#pragma unroll
    for (int f = 0; f < 4; f++)
#pragma unroll
        for (int j = 0; j < 4; j++)
#pragma unroll
            for (int q = 0; q < 4; q++) acc[f][j][q] = 0.f;

    for (int kb = 0; kb < 4; kb++) {
#pragma unroll
        for (int l = 0; l < 2; l++) {
            int cid = tid + l * 256;
            int row = cid >> 2, ck = cid & 3;
            uint4 v = make_uint4(0u, 0u, 0u, 0u);
            int e = e0 + row;
            if (e < N_EDGES)
                v = *(const uint4*)(g_hedge16 + (size_t)e * 128 + kb * 32 + ck * 8);
            *(uint4*)(As + ((row << 2) + (ck ^ (row & 3))) * 8) = v;
        }
#pragma unroll
        for (int l = 0; l < 2; l++) {
            int cid = tid + l * 256;
            int row = cid >> 4, ck = cid & 15;
            uint4 v = *(const uint4*)(g_W2h + (size_t)(kb * 32 + row) * 4096 + j0 + ck * 8);
            *(uint4*)(Bs + ((row << 4) + (ck ^ (row & 7))) * 8) = v;
        }
        __syncthreads();
#pragma unroll
        for (int s = 0; s < 2; s++) {
            unsigned a[4][4];
#pragma unroll
            for (int f = 0; f < 4; f++) {
                int m0 = warp_m * 64 + f * 16;
                int row = m0 + li + (grp & 1) * 8;
                int ck = (s * 2 + (grp >> 1)) ^ (row & 3);
                LDSM4(a[f][0], a[f][1], a[f][2], a[f][3],
                      As_b + ((row << 2) + ck) * 16);
            }
            unsigned b[2][4];
#pragma unroll
            for (int p = 0; p < 2; p++) {
                int n0 = warp_n * 32 + p * 16;
                int row = s * 16 + li + (grp & 1) * 8;
                int ck = ((n0 >> 3) + (grp >> 1)) ^ (row & 7);
                LDSM4T(b[p][0], b[p][1], b[p][2], b[p][3],
                       Bs_b + ((row << 4) + ck) * 16);
            }
#pragma unroll
            for (int f = 0; f < 4; f++) {
                MMA16816(acc[f][0], a[f], b[0][0], b[0][1]);
                MMA16816(acc[f][1], a[f], b[0][2], b[0][3]);
                MMA16816(acc[f][2], a[f], b[1][0], b[1][1]);
                MMA16816(acc[f][3], a[f], b[1][2], b[1][3]);
            }
        }
        __syncthreads();
    }
#pragma unroll
    for (int j = 0; j < 4; j++) {
        int cn = warp_n * 32 + j * 8 + (lane & 3) * 2;
        float bv0 = b2[j0 + cn], bv1 = b2[j0 + cn + 1];
#pragma unroll
        for (int f = 0; f < 4; f++) {
            int r = warp_m * 64 + f * 16 + (lane >> 2);
            int e = e0 + r;
            if (e < N_EDGES) {
                __half2 h = __floats2half2_rn(acc[f][j][0] + bv0, acc[f][j][1] + bv1);
                *(__half2*)(g_We16 + (size_t)e * 4096 + j0 + cn) = h;
            }
            if (e + 8 < N_EDGES) {
                __half2 h = __floats2half2_rn(acc[f][j][2] + bv0, acc[f][j][3] + bv1);
                *(__half2*)(g_We16 + (size_t)(e + 8) * 4096 + j0 + cn) = h;
            }
        }
    }
}

// ---------------- initial agg = conv_bias ----------------
__global__ void k_initagg(const float* __restrict__ cb) {
    int idx = blockIdx.x * 256 + threadIdx.x;   // exactly N_NODES*64
    g_agg[idx] = cb[idx & 63];
}

// ---------------- einsum + scatter: warp per edge, HBM-bound over fp16 We ----------------
__global__ void k_einsum(const int* __restrict__ src, const int* __restrict__ dst) {
    __shared__ float xs[8][64];
    int w = threadIdx.x >> 5, t = threadIdx.x & 31;
    int e = (blockIdx.x << 3) + w;              // exactly N_EDGES
    int s = src[e];
    int j = t << 1;
    float2 v = *(const float2*)(g_h + s * 64 + j);
    xs[w][j] = v.x; xs[w][j + 1] = v.y;
    __syncwarp();
    const __half2* __restrict__ Wr = (const __half2*)(g_We16 + (size_t)e * 4096);
    float ax = 0.f, ay = 0.f;
#pragma unroll 8
    for (int i = 0; i < 64; i++) {
        float xi = xs[w][i];
        float2 wf = __half22float2(Wr[i * 32 + t]);
        ax = fmaf(xi, wf.x, ax);
        ay = fmaf(xi, wf.y, ay);
    }
    int dn = dst[e];
    atomicAdd(g_agg + dn * 64 + j, ax);
    atomicAdd(g_agg + dn * 64 + j + 1, ay);
}

// ---------------- GRU cell: warp per node; also resets agg to bias for next step --------
__global__ void k_gru(const float* __restrict__ bih, const float* __restrict__ bhh,
                      const float* __restrict__ cb) {
    __shared__ float sm[4][64];
    __shared__ float sh[4][64];
    int w = threadIdx.x >> 5, t = threadIdx.x & 31;
    int n = (blockIdx.x << 2) + w;              // exactly N_NODES
    int j = t << 1;
    float2 av = *(const float2*)(g_agg + n * 64 + j);
    sm[w][j] = fmaxf(av.x, 0.f); sm[w][j + 1] = fmaxf(av.y, 0.f);
    float2 hv = *(const float2*)(g_h + n * 64 + j);
    sh[w][j] = hv.x; sh[w][j + 1] = hv.y;
    // reset agg for next step (this kernel is the only consumer)
    float2 cbv = *(const float2*)(cb + j);
    *(float2*)(g_agg + n * 64 + j) = cbv;
    __syncwarp();
    const u64* __restrict__ WX = (const u64*)g_WihT;
    const u64* __restrict__ WH = (const u64*)g_WhhT;
    u64 arx = 0, azx = 0, anx = 0, arh = 0, azh = 0, anh = 0;
#pragma unroll 4
    for (int i = 0; i < 64; i++) {
        float xi = sm[w][i], hi = sh[w][i];
        u64 px = pack2(xi, xi), ph = pack2(hi, hi);
        int base = i * 96 + t;                  // u64 index into [64][192]
        fma2(arx, px, WX[base]);
        fma2(azx, px, WX[base + 32]);
        fma2(anx, px, WX[base + 64]);
        fma2(arh, ph, WH[base]);
        fma2(azh, ph, WH[base + 32]);
        fma2(anh, ph, WH[base + 64]);
    }
    float2 rx = unpack2(arx), zx = unpack2(azx), nx = unpack2(anx);
    float2 rh = unpack2(arh), zh = unpack2(azh), nh = unpack2(anh);
    float r0 = sigf(rx.x + bih[j]       + rh.x + bhh[j]);
    float r1 = sigf(rx.y + bih[j + 1]   + rh.y + bhh[j + 1]);
    float z0 = sigf(zx.x + bih[64 + j]  + zh.x + bhh[64 + j]);
    float z1 = sigf(zx.y + bih[64 + j+1]+ zh.y + bhh[64 + j + 1]);
    float n0 = tanhf(nx.x + bih[128 + j]     + r0 * (nh.x + bhh[128 + j]));
    float n1 = tanhf(nx.y + bih[128 + j + 1] + r1 * (nh.y + bhh[128 + j + 1]));
    float2 o;
    o.x = (1.f - z0) * n0 + z0 * hv.x;
    o.y = (1.f - z1) * n1 + z1 * hv.y;
    *(float2*)(g_h + n * 64 + j) = o;
}

// ---------------- fused Set2Set + head: one block per graph ----------------
__device__ __forceinline__ void lstm_layer(const __half* __restrict__ WT,
                                           const __half* __restrict__ UT,
                                           const float* __restrict__ bih,
                                           const float* __restrict__ bhh,
                                           const float* __restrict__ x, int in_dim,
                                           float* h, float* c, float* g, int tid) {
    float acc = bih[tid] + bhh[tid];
#pragma unroll 4
    for (int i = 0; i < in_dim; i++) acc += x[i] * __half2float(WT[i * 256 + tid]);
#pragma unroll 4
    for (int i = 0; i < 64; i++) acc += h[i] * __half2float(UT[i * 256 + tid]);
    g[tid] = acc;
    __syncthreads();
    if (tid < 64) {
        float ig = sigf(g[tid]);
        float fg = sigf(g[64 + tid]);
        float gg = tanhf(g[128 + tid]);
        float og = sigf(g[192 + tid]);
        float cc = fg * c[tid] + ig * gg;
        c[tid] = cc;
        h[tid] = og * tanhf(cc);
    }
    __syncthreads();
}

__global__ __launch_bounds__(256) void k_set2set(
        const int* __restrict__ gid,
        const float* __restrict__ l0_bih, const float* __restrict__ l0_bhh,
        const float* __restrict__ l12_bih, const float* __restrict__ l12_bhh,
        const float* __restrict__ lin1_W, const float* __restrict__ lin1_b,
        const float* __restrict__ lin2_W, const float* __restrict__ lin2_b,
        float* __restrict__ out) {
    __shared__ float gsh[256];
    __shared__ float hst[3][64], cst[3][64];
    __shared__ float qstar[128];
    __shared__ float m8[8], s8[8];
    __shared__ float r8[8][64];
    __shared__ float t1s[64];
    __shared__ int rng[2];

    const int b = blockIdx.x;
    const int tid = threadIdx.x;
    const int wid = tid >> 5, lane = tid & 31;

    if (tid == 0) {
        int lo = 0, hi = N_NODES;
        while (lo < hi) { int mid = (lo + hi) >> 1; if (gid[mid] < b) lo = mid + 1; else hi = mid; }
        rng[0] = lo;
        lo = 0; hi = N_NODES;
        while (lo < hi) { int mid = (lo + hi) >> 1; if (gid[mid] < b + 1) lo = mid + 1; else hi = mid; }
        rng[1] = lo;
    }
    if (tid < 128) qstar[tid] = 0.f;
    if (tid < 64) {
        hst[0][tid] = 0.f; hst[1][tid] = 0.f; hst[2][tid] = 0.f;
        cst[0][tid] = 0.f; cst[1][tid] = 0.f; cst[2][tid] = 0.f;
    }
    __syncthreads();
    const int ns = rng[0], ne = rng[1];

    for (int step = 0; step < S2S_STEPS; step++) {
        lstm_layer(g_L0ihT, g_L0hhT, l0_bih, l0_bhh, qstar, 128,
                   hst[0], cst[0], gsh, tid);
        lstm_layer(g_L12ihT, g_L12hhT, l12_bih, l12_bhh, hst[0], 64,
                   hst[1], cst[1], gsh, tid);
        lstm_layer(g_L12ihT + 16384, g_L12hhT + 16384, l12_bih + 256, l12_bhh + 256,
                   hst[1], 64, hst[2], cst[2], gsh, tid);
        // attention with streaming softmax; q = hst[2]
        float qa = hst[2][lane], qb = hst[2][32 + lane];
        float m = -INFINITY, ssum = 0.f, r0 = 0.f, r1 = 0.f;
        for (int n = ns + wid; n < ne; n += 8) {
            float o0 = g_h[n * 64 + lane];
            float o1 = g_h[n * 64 + 32 + lane];
            float part = o0 * qa + o1 * qb;
#pragma unroll
            for (int o = 16; o; o >>= 1) part += __shfl_xor_sync(0xffffffffu, part, o);
            if (part > m) {
                float sc = expf(m - part);
                ssum = ssum * sc + 1.f;
                r0 = r0 * sc + o0;
                r1 = r1 * sc + o1;
                m = part;
            } else {
                float wg = expf(part - m);
                ssum += wg;
                r0 += wg * o0;
                r1 += wg * o1;
            }
        }
        if (lane == 0) { m8[wid] = m; s8[wid] = ssum; }
        r8[wid][lane] = r0;
        r8[wid][32 + lane] = r1;
        __syncthreads();
        if (tid < 64) {
            float M = -INFINITY;
#pragma unroll
            for (int w = 0; w < 8; w++) if (s8[w] > 0.f) M = fmaxf(M, m8[w]);
            float S = 0.f, R = 0.f;
#pragma unroll
            for (int w = 0; w < 8; w++) {
                if (s8[w] > 0.f) {
                    float sc = expf(m8[w] - M);
                    S += s8[w] * sc;
                    R += r8[w][tid] * sc;
                }
            }
            qstar[tid] = hst[2][tid];
            qstar[64 + tid] = (S > 0.f) ? (R / S) : 0.f;
        }
        __syncthreads();
    }
    // head: t1 = relu(qstar @ lin1 + b1); out = t1 @ lin2 + b2
    if (tid < 64) {
        float acc = lin1_b[tid];
#pragma unroll 4
        for (int i = 0; i < 128; i++) acc += qstar[i] * lin1_W[i * 64 + tid];
        t1s[tid] = fmaxf(acc, 0.f);
    }
    __syncthreads();
    if (tid < OUT_DIM) {
        float acc = lin2_b[tid];
#pragma unroll 4
        for (int d = 0; d < 64; d++) acc += t1s[d] * lin2_W[d * OUT_DIM + tid];
        out[b * OUT_DIM + tid] = acc;
    }
}

// ---------------- launcher ----------------
extern "C" void kernel_launch(void* const* d_in, const int* in_sizes, int n_in,
                              void* d_out, int out_size) {
    const float* node_feat = (const float*)d_in[0];
    const float* edge_feat = (const float*)d_in[1];
    const int*   src       = (const int*)d_in[2];
    const int*   dst       = (const int*)d_in[3];
    const int*   gid       = (const int*)d_in[4];
    // d_in[5] = num_graphs (unused; B fixed)
    const float* lin0_W = (const float*)d_in[6];
    const float* lin0_b = (const float*)d_in[7];
    const float* em_W1  = (const float*)d_in[8];
    const float* em_b1  = (const float*)d_in[9];
    const float* em_W2  = (const float*)d_in[10];
    const float* em_b2  = (const float*)d_in[11];
    const float* conv_bias = (const float*)d_in[12];
    const float* gru_Wih = (const float*)d_in[13];
    const float* gru_Whh = (const float*)d_in[14];
    const float* gru_bih = (const float*)d_in[15];
    const float* gru_bhh = (const float*)d_in[16];
    const float* l0_Wih = (const float*)d_in[17];
    const float* l0_Whh = (const float*)d_in[18];
    const float* l0_bih = (const float*)d_in[19];
    const float* l0_bhh = (const float*)d_in[20];
    const float* l12_Wih = (const float*)d_in[21];
    const float* l12_Whh = (const float*)d_in[22];
    const float* l12_bih = (const float*)d_in[23];
    const float* l12_bhh = (const float*)d_in[24];
    const float* lin1_W = (const float*)d_in[25];
    const float* lin1_b = (const float*)d_in[26];
    const float* lin2_W = (const float*)d_in[27];
    const float* lin2_b = (const float*)d_in[28];
    float* out = (float*)d_out;

    (void)in_sizes; (void)n_in; (void)out_size;

    k_prep<<<128, 256>>>(gru_Wih, gru_Whh, l0_Wih, l0_Whh, l12_Wih, l12_Whh, em_W2);
    k_lin0<<<(N_NODES * 64) / 256, 256>>>(node_feat, lin0_W, lin0_b);
    k_edgehid<<<(N_EDGES * EHID) / 256, 256>>>(edge_feat, em_W1, em_b1);
    k_gemm<<<dim3(DDIM / BN, (N_EDGES + BM - 1) / BM), 256>>>(em_b2);

    k_initagg<<<(N_NODES * 64) / 256, 256>>>(conv_bias);
    for (int s = 0; s < MP_STEPS; s++) {
        k_einsum<<<N_EDGES / 8, 256>>>(src, dst);
        k_gru<<<N_NODES / 4, 128>>>(gru_bih, gru_bhh, conv_bias);
    }

    k_set2set<<<NB, 256>>>(gid, l0_bih, l0_bhh, l12_bih, l12_bhh,
                           lin1_W, lin1_b, lin2_W, lin2_b, out);
}

// round 10
// speedup vs baseline: 2.7361x; 1.1831x over previous
#include <cuda_runtime.h>
#include <cuda_fp16.h>
#include <math.h>

typedef unsigned long long u64;

#define N_NODES 10000
#define N_EDGES 50000
#define NB      500
#define D       64
#define NODE_IN 15
#define EDGE_IN 5
#define EHID    128
#define DDIM    4096   // D*D
#define OUT_DIM 12
#define MP_STEPS 6
#define S2S_STEPS 6

// ---------------- scratch (device globals; no allocation allowed) ----------------
__device__ __align__(16) __half g_We16[(size_t)N_EDGES * DDIM]; // 410 MB fp16
__device__ __align__(16) __half g_hedge16[N_EDGES * EHID];      // 12.8 MB fp16
__device__ __align__(16) __half g_W2h[EHID * DDIM];             // 1 MB fp16
__device__ __align__(16) float g_h[N_NODES * D];                // node state
__device__ __align__(16) float g_agg[N_NODES * D];
// GRU weights (fp16, transposed: [64][192])
__device__ __align__(16) __half g_WihT16[D * 3 * D];
__device__ __align__(16) __half g_WhhT16[D * 3 * D];
// LSTM weights (fp16, transposed: [in][256])
__device__ __align__(16) __half g_L0ihT[2 * D * 4 * D];  // [128][256]
__device__ __align__(16) __half g_L0hhT[D * 4 * D];      // [64][256]
__device__ __align__(16) __half g_L12ihT[2 * D * 4 * D]; // 2 x [64][256]
__device__ __align__(16) __half g_L12hhT[2 * D * 4 * D];

// ---------------- helpers ----------------
__device__ __forceinline__ float sigf(float x) { return 1.f / (1.f + expf(-x)); }
__device__ __forceinline__ unsigned sm_u32(const void* p) {
    return (unsigned)__cvta_generic_to_shared(p);
}
#define LDSM4(r0,r1,r2,r3,addr) \
    asm volatile("ldmatrix.sync.aligned.m8n8.x4.shared.b16 {%0,%1,%2,%3}, [%4];" \
        : "=r"(r0),"=r"(r1),"=r"(r2),"=r"(r3) : "r"(addr))
#define LDSM4T(r0,r1,r2,r3,addr) \
    asm volatile("ldmatrix.sync.aligned.m8n8.x4.trans.shared.b16 {%0,%1,%2,%3}, [%4];" \
        : "=r"(r0),"=r"(r1),"=r"(r2),"=r"(r3) : "r"(addr))
#define MMA16816(d,a,b0,b1) \
    asm volatile("mma.sync.aligned.m16n8k16.row.col.f32.f16.f16.f32 " \
        "{%0,%1,%2,%3}, {%4,%5,%6,%7}, {%8,%9}, {%0,%1,%2,%3};" \
        : "+f"((d)[0]),"+f"((d)[1]),"+f"((d)[2]),"+f"((d)[3]) \
        : "r"((a)[0]),"r"((a)[1]),"r"((a)[2]),"r"((a)[3]), "r"(b0),"r"(b1))
__device__ __forceinline__ void cp16(unsigned d, const void* s, int sz) {
    asm volatile("cp.async.cg.shared.global [%0], [%1], 16, %2;" :: "r"(d), "l"(s), "r"(sz));
}
#define CP_COMMIT() asm volatile("cp.async.commit_group;")
#define CP_WAIT(n)  asm volatile("cp.async.wait_group %0;" :: "n"(n))

// ---------------- prep: transpose small weight matrices + fp16 conversions ---------------
__global__ void k_prep(const float* __restrict__ gWih, const float* __restrict__ gWhh,
                       const float* __restrict__ l0ih, const float* __restrict__ l0hh,
                       const float* __restrict__ l12ih, const float* __restrict__ l12hh,
                       const float* __restrict__ W2) {
    int tid = blockIdx.x * blockDim.x + threadIdx.x;
    int nt  = gridDim.x * blockDim.x;
    for (int x = tid; x < 192 * 64; x += nt) {
        int j = x / 64, i = x % 64;
        g_WihT16[i * 192 + j] = __float2half(gWih[j * 64 + i]);
        g_WhhT16[i * 192 + j] = __float2half(gWhh[j * 64 + i]);
    }
    for (int x = tid; x < 256 * 128; x += nt) {
        int j = x / 128, i = x % 128;
        g_L0ihT[i * 256 + j] = __float2half(l0ih[j * 128 + i]);
    }
    for (int x = tid; x < 256 * 64; x += nt) {
        int j = x / 64, i = x % 64;
        g_L0hhT[i * 256 + j] = __float2half(l0hh[j * 64 + i]);
    }
    for (int x = tid; x < 2 * 256 * 64; x += nt) {
        int l = x / 16384, rem = x % 16384;
        int j = rem / 64, i = rem % 64;
        g_L12ihT[l * 16384 + i * 256 + j] = __float2half(l12ih[l * 16384 + j * 64 + i]);
        g_L12hhT[l * 16384 + i * 256 + j] = __float2half(l12hh[l * 16384 + j * 64 + i]);
    }
    for (int x = tid; x < EHID * DDIM; x += nt)
        g_W2h[x] = __float2half(W2[x]);
}

// ---------------- lin0: out = relu(node_feat @ lin0_W + b) ----------------
__global__ void k_lin0(const float* __restrict__ nf, const float* __restrict__ W,
                       const float* __restrict__ b) {
    int idx = blockIdx.x * 256 + threadIdx.x;   // exactly N_NODES*64
    int n = idx >> 6, d = idx & 63;
    float acc = b[d];
#pragma unroll
    for (int i = 0; i < NODE_IN; i++) acc += nf[n * NODE_IN + i] * W[i * 64 + d];
    g_h[idx] = fmaxf(acc, 0.f);
}

// ---------------- edge hidden (fp16 out): h = relu(edge_feat @ W1 + b1) ----------------
__global__ void k_edgehid(const float* __restrict__ ef, const float* __restrict__ W1,
                          const float* __restrict__ b1) {
    int idx = blockIdx.x * 256 + threadIdx.x;   // exactly N_EDGES*128
    int e = idx >> 7, k = idx & 127;
    float acc = b1[k];
#pragma unroll
    for (int i = 0; i < EDGE_IN; i++) acc += ef[e * EDGE_IN + i] * W1[i * EHID + k];
    g_hedge16[idx] = __float2half(fmaxf(acc, 0.f));
}

// ---------------- big GEMM via HMMA + cp.async double buffering ----------------
#define BM 128
#define BN 128
#define BK 32
__global__ __launch_bounds__(256, 2) void k_gemm(const float* __restrict__ b2) {
    __shared__ __half As[2][BM * BK];   // 2 x 8 KB, chunk-swizzled
    __shared__ __half Bs[2][BK * BN];   // 2 x 8 KB, chunk-swizzled
    const int tid = threadIdx.x;
    const int wid = tid >> 5, lane = tid & 31;
    const int warp_m = wid & 1, warp_n = wid >> 1;
    const int e0 = blockIdx.y * BM;
    const int j0 = blockIdx.x * BN;
    const int li = lane & 7, grp = lane >> 3;
    const unsigned As_b = sm_u32(As), Bs_b = sm_u32(Bs);

    // fill-lane mapping (constant per thread)
    const int a_row0 = tid >> 2,  a_ck = tid & 3;    // + 64 rows for second chunk
    const int b_row0 = tid >> 4,  b_ck = tid & 15;   // + 16 rows for second chunk

    float acc[4][4][4];
#pragma unroll
    for (int f = 0; f < 4; f++)
#pragma unroll
        for (int j = 0; j < 4; j++)
#pragma unroll
            for (int q = 0; q < 4; q++) acc[f][j][q] = 0.f;

#define ISSUE_STAGE(kb, st) do {                                                   \
    _Pragma("unroll")                                                              \
    for (int l = 0; l < 2; l++) {                                                  \
        int row = a_row0 + l * 64;                                                 \
        int e = e0 + row;                                                          \
        unsigned dsta = As_b + (st) * 8192 +                                       \
            (((row << 2) + (a_ck ^ (row & 3))) * 16);                              \
        cp16(dsta, g_hedge16 + (size_t)e * 128 + (kb) * 32 + a_ck * 8,             \
             (e < N_EDGES) ? 16 : 0);                                              \
    }                                                                              \
    _Pragma("unroll")                                                              \
    for (int l = 0; l < 2; l++) {                                                  \
        int row = b_row0 + l * 16;                                                 \
        unsigned dstb = Bs_b + (st) * 8192 +                                       \
            (((row << 4) + (b_ck ^ (row & 7))) * 16);                              \
        cp16(dstb, g_W2h + (size_t)((kb) * 32 + row) * 4096 + j0 + b_ck * 8, 16);  \
    }                                                                              \
    CP_COMMIT();                                                                   \
} while (0)

    ISSUE_STAGE(0, 0);
#pragma unroll
    for (int kb = 0; kb < 4; kb++) {
        if (kb < 3) { ISSUE_STAGE(kb + 1, (kb + 1) & 1); CP_WAIT(1); }
        else        { CP_WAIT(0); }
        __syncthreads();
        const unsigned Abase = As_b + (kb & 1) * 8192;
        const unsigned Bbase = Bs_b + (kb & 1) * 8192;
#pragma unroll
        for (int s = 0; s < 2; s++) {
            unsigned a[4][4];
#pragma unroll
            for (int f = 0; f < 4; f++) {
                int m0 = warp_m * 64 + f * 16;
                int row = m0 + li + (grp & 1) * 8;
                int ck = (s * 2 + (grp >> 1)) ^ (row & 3);
                LDSM4(a[f][0], a[f][1], a[f][2], a[f][3],
                      Abase + ((row << 2) + ck) * 16);
            }
            unsigned b[2][4];
#pragma unroll
            for (int p = 0; p < 2; p++) {
                int n0 = warp_n * 32 + p * 16;
                int row = s * 16 + li + (grp & 1) * 8;
                int ck = ((n0 >> 3) + (grp >> 1)) ^ (row & 7);
                LDSM4T(b[p][0], b[p][1], b[p][2], b[p][3],
                       Bbase + ((row << 4) + ck) * 16);
            }
#pragma unroll
            for (int f = 0; f < 4; f++) {
                MMA16816(acc[f][0], a[f], b[0][0], b[0][1]);
                MMA16816(acc[f][1], a[f], b[0][2], b[0][3]);
                MMA16816(acc[f][2], a[f], b[1][0], b[1][1]);
                MMA16816(acc[f][3], a[f], b[1][2], b[1][3]);
            }
        }
        __syncthreads();
    }
#pragma unroll
    for (int j = 0; j < 4; j++) {
        int cn = warp_n * 32 + j * 8 + (lane & 3) * 2;
        float bv0 = b2[j0 + cn], bv1 = b2[j0 + cn + 1];
#pragma unroll
        for (int f = 0; f < 4; f++) {
            int r = warp_m * 64 + f * 16 + (lane >> 2);
            int e = e0 + r;
            if (e < N_EDGES) {
                __half2 h = __floats2half2_rn(acc[f][j][0] + bv0, acc[f][j][1] + bv1);
                *(__half2*)(g_We16 + (size_t)e * 4096 + j0 + cn) = h;
            }
            if (e + 8 < N_EDGES) {
                __half2 h = __floats2half2_rn(acc[f][j][2] + bv0, acc[f][j][3] + bv1);
                *(__half2*)(g_We16 + (size_t)(e + 8) * 4096 + j0 + cn) = h;
            }
        }
    }
}

// ---------------- initial agg = conv_bias ----------------
__global__ void k_initagg(const float* __restrict__ cb) {
    int idx = blockIdx.x * 256 + threadIdx.x;   // exactly N_NODES*64
    g_agg[idx] = cb[idx & 63];
}

// ---------------- einsum + scatter: warp per edge, uint4 loads over fp16 We -----------
__global__ void k_einsum(const int* __restrict__ src, const int* __restrict__ dst) {
    __shared__ float xs[8][64];
    int w = threadIdx.x >> 5, t = threadIdx.x & 31;
    int e = (blockIdx.x << 3) + w;              // exactly N_EDGES
    int s = src[e];
    int j2 = t << 1;
    float2 v = *(const float2*)(g_h + s * 64 + j2);
    xs[w][j2] = v.x; xs[w][j2 + 1] = v.y;
    __syncwarp();
    const uint4* __restrict__ W4 = (const uint4*)(g_We16 + (size_t)e * 4096);
    const int cg = t & 7, rg = t >> 3;
    float acc[8];
#pragma unroll
    for (int k = 0; k < 8; k++) acc[k] = 0.f;
#pragma unroll
    for (int i = 0; i < 16; i++) {
        int r = i * 4 + rg;
        uint4 q = W4[r * 8 + cg];
        float xi = xs[w][r];
        float2 f0 = __half22float2(*(__half2*)&q.x);
        float2 f1 = __half22float2(*(__half2*)&q.y);
        float2 f2 = __half22float2(*(__half2*)&q.z);
        float2 f3 = __half22float2(*(__half2*)&q.w);
        acc[0] = fmaf(xi, f0.x, acc[0]); acc[1] = fmaf(xi, f0.y, acc[1]);
        acc[2] = fmaf(xi, f1.x, acc[2]); acc[3] = fmaf(xi, f1.y, acc[3]);
        acc[4] = fmaf(xi, f2.x, acc[4]); acc[5] = fmaf(xi, f2.y, acc[5]);
        acc[6] = fmaf(xi, f3.x, acc[6]); acc[7] = fmaf(xi, f3.y, acc[7]);
    }
#pragma unroll
    for (int k = 0; k < 8; k++) {
        acc[k] += __shfl_xor_sync(0xffffffffu, acc[k], 8);
        acc[k] += __shfl_xor_sync(0xffffffffu, acc[k], 16);
    }
    int dn = dst[e];
    int k0 = rg * 2;
    int col = cg * 8 + k0;
    atomicAdd(g_agg + dn * 64 + col,     acc[k0]);
    atomicAdd(g_agg + dn * 64 + col + 1, acc[k0 + 1]);
}

// ---------------- GRU cell: smem-cached fp16 weights, 8 warps/block, shfl broadcast -----
__global__ __launch_bounds__(256) void k_gru(const float* __restrict__ bih,
                                             const float* __restrict__ bhh,
                                             const float* __restrict__ cb) {
    __shared__ __half2 sW[64 * 96];   // 24 KB  Wih^T [64][192] as half2 pairs
    __shared__ __half2 sU[64 * 96];   // 24 KB  Whh^T
    const int tid = threadIdx.x;
    {
        const uint4* gw = (const uint4*)g_WihT16;
        const uint4* gu = (const uint4*)g_WhhT16;
        uint4* dw = (uint4*)sW;
        uint4* du = (uint4*)sU;
        for (int i = tid; i < 1536; i += 256) { dw[i] = gw[i]; du[i] = gu[i]; }
    }
    __syncthreads();
    const int w = tid >> 5, t = tid & 31;
    const int n = blockIdx.x * 8 + w;           // exactly N_NODES (grid 1250)
    const int j = t << 1;
    float2 av = *(const float2*)(g_agg + n * 64 + j);
    float2 x2; x2.x = fmaxf(av.x, 0.f); x2.y = fmaxf(av.y, 0.f);
    float2 hv = *(const float2*)(g_h + n * 64 + j);
    *(float2*)(g_agg + n * 64 + j) = *(const float2*)(cb + j);   // reset for next step

    float rx0 = 0.f, rx1 = 0.f, zx0 = 0.f, zx1 = 0.f, nx0 = 0.f, nx1 = 0.f;
    float rh0 = 0.f, rh1 = 0.f, zh0 = 0.f, zh1 = 0.f, nh0 = 0.f, nh1 = 0.f;
#pragma unroll
    for (int i = 0; i < 64; i++) {
        float xi = __shfl_sync(0xffffffffu, (i & 1) ? x2.y : x2.x, i >> 1);
        float hi = __shfl_sync(0xffffffffu, (i & 1) ? hv.y : hv.x, i >> 1);
        float2 wr = __half22float2(sW[i * 96 + t]);
        float2 wz = __half22float2(sW[i * 96 + 32 + t]);
        float2 wn = __half22float2(sW[i * 96 + 64 + t]);
        float2 ur = __half22float2(sU[i * 96 + t]);
        float2 uz = __half22float2(sU[i * 96 + 32 + t]);
        float2 un = __half22float2(sU[i * 96 + 64 + t]);
        rx0 = fmaf(xi, wr.x, rx0); rx1 = fmaf(xi, wr.y, rx1);
        zx0 = fmaf(xi, wz.x, zx0); zx1 = fmaf(xi, wz.y, zx1);
        nx0 = fmaf(xi, wn.x, nx0); nx1 = fmaf(xi, wn.y, nx1);
        rh0 = fmaf(hi, ur.x, rh0); rh1 = fmaf(hi, ur.y, rh1);
        zh0 = fmaf(hi, uz.x, zh0); zh1 = fmaf(hi, uz.y, zh1);
        nh0 = fmaf(hi, un.x, nh0); nh1 = fmaf(hi, un.y, nh1);
    }
    float r0 = sigf(rx0 + bih[j]         + rh0 + bhh[j]);
    float r1 = sigf(rx1 + bih[j + 1]     + rh1 + bhh[j + 1]);
    float z0 = sigf(zx0 + bih[64 + j]    + zh0 + bhh[64 + j]);
    float z1 = sigf(zx1 + bih[64 + j + 1]+ zh1 + bhh[64 + j + 1]);
    float n0 = tanhf(nx0 + bih[128 + j]     + r0 * (nh0 + bhh[128 + j]));
    float n1 = tanhf(nx1 + bih[128 + j + 1] + r1 * (nh1 + bhh[128 + j + 1]));
    float2 o;
    o.x = (1.f - z0) * n0 + z0 * hv.x;
    o.y = (1.f - z1) * n1 + z1 * hv.y;
    *(float2*)(g_h + n * 64 + j) = o;
}

// ---------------- fused Set2Set + head: one block per graph ----------------
__device__ __forceinline__ void lstm_layer(const __half* __restrict__ WT,
                                           const __half* __restrict__ UT,
                                           const float* __restrict__ bih,
                                           const float* __restrict__ bhh,
                                           const float* __restrict__ x, int in_dim,
                                           float* h, float* c, float* g, int tid) {
    float acc = bih[tid] + bhh[tid];
#pragma unroll 4
    for (int i = 0; i < in_dim; i++) acc += x[i] * __half2float(WT[i * 256 + tid]);
#pragma unroll 4
    for (int i = 0; i < 64; i++) acc += h[i] * __half2float(UT[i * 256 + tid]);
    g[tid] = acc;
    __syncthreads();
    if (tid < 64) {
        float ig = sigf(g[tid]);
        float fg = sigf(g[64 + tid]);
        float gg = tanhf(g[128 + tid]);
        float og = sigf(g[192 + tid]);
        float cc = fg * c[tid] + ig * gg;
        c[tid] = cc;
        h[tid] = og * tanhf(cc);
    }
    __syncthreads();
}

__global__ __launch_bounds__(256) void k_set2set(
        const int* __restrict__ gid,
        const float* __restrict__ l0_bih, const float* __restrict__ l0_bhh,
        const float* __restrict__ l12_bih, const float* __restrict__ l12_bhh,
        const float* __restrict__ lin1_W, const float* __restrict__ lin1_b,
        const float* __restrict__ lin2_W, const float* __restrict__ lin2_b,
        float* __restrict__ out) {
    __shared__ float gsh[256];
    __shared__ float hst[3][64], cst[3][64];
    __shared__ float qstar[128];
    __shared__ float m8[8], s8[8];
    __shared__ float r8[8][64];
    __shared__ float t1s[64];
    __shared__ int rng[2];

    const int b = blockIdx.x;
    const int tid = threadIdx.x;
    const int wid = tid >> 5, lane = tid & 31;

    if (tid == 0) {
        int lo = 0, hi = N_NODES;
        while (lo < hi) { int mid = (lo + hi) >> 1; if (gid[mid] < b) lo = mid + 1; else hi = mid; }
        rng[0] = lo;
        lo = 0; hi = N_NODES;
        while (lo < hi) { int mid = (lo + hi) >> 1; if (gid[mid] < b + 1) lo = mid + 1; else hi = mid; }
        rng[1] = lo;
    }
    if (tid < 128) qstar[tid] = 0.f;
    if (tid < 64) {
        hst[0][tid] = 0.f; hst[1][tid] = 0.f; hst[2][tid] = 0.f;
        cst[0][tid] = 0.f; cst[1][tid] = 0.f; cst[2][tid] = 0.f;
    }
    __syncthreads();
    const int ns = rng[0], ne = rng[1];

    for (int step = 0; step < S2S_STEPS; step++) {
        lstm_layer(g_L0ihT, g_L0hhT, l0_bih, l0_bhh, qstar, 128,
                   hst[0], cst[0], gsh, tid);
        lstm_layer(g_L12ihT, g_L12hhT, l12_bih, l12_bhh, hst[0], 64,
                   hst[1], cst[1], gsh, tid);
        lstm_layer(g_L12ihT + 16384, g_L12hhT + 16384, l12_bih + 256, l12_bhh + 256,
                   hst[1], 64, hst[2], cst[2], gsh, tid);
        // attention with streaming softmax; q = hst[2]
        float qa = hst[2][lane], qb = hst[2][32 + lane];
        float m = -INFINITY, ssum = 0.f, r0 = 0.f, r1 = 0.f;
        for (int n = ns + wid; n < ne; n += 8) {
            float o0 = g_h[n * 64 + lane];
            float o1 = g_h[n * 64 + 32 + lane];
            float part = o0 * qa + o1 * qb;
#pragma unroll
            for (int o = 16; o; o >>= 1) part += __shfl_xor_sync(0xffffffffu, part, o);
            if (part > m) {
                float sc = expf(m - part);
                ssum = ssum * sc + 1.f;
                r0 = r0 * sc + o0;
                r1 = r1 * sc + o1;
                m = part;
            } else {
                float wg = expf(part - m);
                ssum += wg;
                r0 += wg * o0;
                r1 += wg * o1;
            }
        }
        if (lane == 0) { m8[wid] = m; s8[wid] = ssum; }
        r8[wid][lane] = r0;
        r8[wid][32 + lane] = r1;
        __syncthreads();
        if (tid < 64) {
            float M = -INFINITY;
#pragma unroll
            for (int w = 0; w < 8; w++) if (s8[w] > 0.f) M = fmaxf(M, m8[w]);
            float S = 0.f, R = 0.f;
#pragma unroll
            for (int w = 0; w < 8; w++) {
                if (s8[w] > 0.f) {
                    float sc = expf(m8[w] - M);
                    S += s8[w] * sc;
                    R += r8[w][tid] * sc;
                }
            }
            qstar[tid] = hst[2][tid];
            qstar[64 + tid] = (S > 0.f) ? (R / S) : 0.f;
        }
        __syncthreads();
    }
    // head: t1 = relu(qstar @ lin1 + b1); out = t1 @ lin2 + b2
    if (tid < 64) {
        float acc = lin1_b[tid];
#pragma unroll 4
        for (int i = 0; i < 128; i++) acc += qstar[i] * lin1_W[i * 64 + tid];
        t1s[tid] = fmaxf(acc, 0.f);
    }
    __syncthreads();
    if (tid < OUT_DIM) {
        float acc = lin2_b[tid];
#pragma unroll 4
        for (int d = 0; d < 64; d++) acc += t1s[d] * lin2_W[d * OUT_DIM + tid];
        out[b * OUT_DIM + tid] = acc;
    }
}

// ---------------- launcher ----------------
extern "C" void kernel_launch(void* const* d_in, const int* in_sizes, int n_in,
                              void* d_out, int out_size) {
    const float* node_feat = (const float*)d_in[0];
    const float* edge_feat = (const float*)d_in[1];
    const int*   src       = (const int*)d_in[2];
    const int*   dst       = (const int*)d_in[3];
    const int*   gid       = (const int*)d_in[4];
    // d_in[5] = num_graphs (unused; B fixed)
    const float* lin0_W = (const float*)d_in[6];
    const float* lin0_b = (const float*)d_in[7];
    const float* em_W1  = (const float*)d_in[8];
    const float* em_b1  = (const float*)d_in[9];
    const float* em_W2  = (const float*)d_in[10];
    const float* em_b2  = (const float*)d_in[11];
    const float* conv_bias = (const float*)d_in[12];
    const float* gru_Wih = (const float*)d_in[13];
    const float* gru_Whh = (const float*)d_in[14];
    const float* gru_bih = (const float*)d_in[15];
    const float* gru_bhh = (const float*)d_in[16];
    const float* l0_Wih = (const float*)d_in[17];
    const float* l0_Whh = (const float*)d_in[18];
    const float* l0_bih = (const float*)d_in[19];
    const float* l0_bhh = (const float*)d_in[20];
    const float* l12_Wih = (const float*)d_in[21];
    const float* l12_Whh = (const float*)d_in[22];
    const float* l12_bih = (const float*)d_in[23];
    const float* l12_bhh = (const float*)d_in[24];
    const float* lin1_W = (const float*)d_in[25];
    const float* lin1_b = (const float*)d_in[26];
    const float* lin2_W = (const float*)d_in[27];
    const float* lin2_b = (const float*)d_in[28];
    float* out = (float*)d_out;

    (void)in_sizes; (void)n_in; (void)out_size;

    k_prep<<<128, 256>>>(gru_Wih, gru_Whh, l0_Wih, l0_Whh, l12_Wih, l12_Whh, em_W2);
    k_lin0<<<(N_NODES * 64) / 256, 256>>>(node_feat, lin0_W, lin0_b);
    k_edgehid<<<(N_EDGES * EHID) / 256, 256>>>(edge_feat, em_W1, em_b1);
    k_gemm<<<dim3(DDIM / BN, (N_EDGES + BM - 1) / BM), 256>>>(em_b2);

    k_initagg<<<(N_NODES * 64) / 256, 256>>>(conv_bias);
    for (int s = 0; s < MP_STEPS; s++) {
        k_einsum<<<N_EDGES / 8, 256>>>(src, dst);
        k_gru<<<N_NODES / 8, 256>>>(gru_bih, gru_bhh, conv_bias);
    }

    k_set2set<<<NB, 256>>>(gid, l0_bih, l0_bhh, l12_bih, l12_bhh,
                           lin1_W, lin1_b, lin2_W, lin2_b, out);
}

// round 11
// speedup vs baseline: 2.8739x; 1.0503x over previous
#include <cuda_runtime.h>
#include <cuda_fp16.h>
#include <math.h>

typedef unsigned long long u64;

#define N_NODES 10000
#define N_EDGES 50000
#define NB      500
#define D       64
#define NODE_IN 15
#define EDGE_IN 5
#define EHID    128
#define DDIM    4096   // D*D
#define OUT_DIM 12
#define MP_STEPS 6
#define S2S_STEPS 6

// ---------------- scratch (device globals; no allocation allowed) ----------------
__device__ __align__(16) __half g_We16[(size_t)N_EDGES * DDIM]; // 410 MB fp16
__device__ __align__(16) __half g_hedge16[N_EDGES * EHID];      // 12.8 MB fp16
__device__ __align__(16) __half g_W2h[EHID * DDIM];             // 1 MB fp16
__device__ __align__(16) float g_h[N_NODES * D];                // node state
__device__ __align__(16) float g_agg[N_NODES * D];
// GRU weights (fp16, transposed: [64][192])
__device__ __align__(16) __half g_WihT16[D * 3 * D];
__device__ __align__(16) __half g_WhhT16[D * 3 * D];
// LSTM weights (fp16, transposed: [in][256])
__device__ __align__(16) __half g_L0ihT[2 * D * 4 * D];  // [128][256]
__device__ __align__(16) __half g_L0hhT[D * 4 * D];      // [64][256]
__device__ __align__(16) __half g_L12ihT[2 * D * 4 * D]; // 2 x [64][256]
__device__ __align__(16) __half g_L12hhT[2 * D * 4 * D];

// ---------------- helpers ----------------
__device__ __forceinline__ float sigf(float x) { return 1.f / (1.f + expf(-x)); }
__device__ __forceinline__ unsigned sm_u32(const void* p) {
    return (unsigned)__cvta_generic_to_shared(p);
}
#define LDSM4(r0,r1,r2,r3,addr) \
    asm volatile("ldmatrix.sync.aligned.m8n8.x4.shared.b16 {%0,%1,%2,%3}, [%4];" \
        : "=r"(r0),"=r"(r1),"=r"(r2),"=r"(r3) : "r"(addr))
#define LDSM4T(r0,r1,r2,r3,addr) \
    asm volatile("ldmatrix.sync.aligned.m8n8.x4.trans.shared.b16 {%0,%1,%2,%3}, [%4];" \
        : "=r"(r0),"=r"(r1),"=r"(r2),"=r"(r3) : "r"(addr))
#define MMA16816(d,a,b0,b1) \
    asm volatile("mma.sync.aligned.m16n8k16.row.col.f32.f16.f16.f32 " \
        "{%0,%1,%2,%3}, {%4,%5,%6,%7}, {%8,%9}, {%0,%1,%2,%3};" \
        : "+f"((d)[0]),"+f"((d)[1]),"+f"((d)[2]),"+f"((d)[3]) \
        : "r"((a)[0]),"r"((a)[1]),"r"((a)[2]),"r"((a)[3]), "r"(b0),"r"(b1))
__device__ __forceinline__ void cp16(unsigned d, const void* s, int sz) {
    asm volatile("cp.async.cg.shared.global [%0], [%1], 16, %2;" :: "r"(d), "l"(s), "r"(sz));
}
#define CP_COMMIT() asm volatile("cp.async.commit_group;")
#define CP_WAIT(n)  asm volatile("cp.async.wait_group %0;" :: "n"(n))

// ---------------- prep: transpose small weight matrices + fp16 conversions ---------------
__global__ void k_prep(const float* __restrict__ gWih, const float* __restrict__ gWhh,
                       const float* __restrict__ l0ih, const float* __restrict__ l0hh,
                       const float* __restrict__ l12ih, const float* __restrict__ l12hh,
                       const float* __restrict__ W2) {
    int tid = blockIdx.x * blockDim.x + threadIdx.x;
    int nt  = gridDim.x * blockDim.x;
    for (int x = tid; x < 192 * 64; x += nt) {
        int j = x / 64, i = x % 64;
        g_WihT16[i * 192 + j] = __float2half(gWih[j * 64 + i]);
        g_WhhT16[i * 192 + j] = __float2half(gWhh[j * 64 + i]);
    }
    for (int x = tid; x < 256 * 128; x += nt) {
        int j = x / 128, i = x % 128;
        g_L0ihT[i * 256 + j] = __float2half(l0ih[j * 128 + i]);
    }
    for (int x = tid; x < 256 * 64; x += nt) {
        int j = x / 64, i = x % 64;
        g_L0hhT[i * 256 + j] = __float2half(l0hh[j * 64 + i]);
    }
    for (int x = tid; x < 2 * 256 * 64; x += nt) {
        int l = x / 16384, rem = x % 16384;
        int j = rem / 64, i = rem % 64;
        g_L12ihT[l * 16384 + i * 256 + j] = __float2half(l12ih[l * 16384 + j * 64 + i]);
        g_L12hhT[l * 16384 + i * 256 + j] = __float2half(l12hh[l * 16384 + j * 64 + i]);
    }
    for (int x = tid; x < EHID * DDIM; x += nt)
        g_W2h[x] = __float2half(W2[x]);
}

// ---------------- lin0 + agg init: out = relu(nf @ lin0_W + b); agg = conv_bias --------
__global__ void k_lin0(const float* __restrict__ nf, const float* __restrict__ W,
                       const float* __restrict__ b, const float* __restrict__ cb) {
    int idx = blockIdx.x * 256 + threadIdx.x;   // exactly N_NODES*64
    int n = idx >> 6, d = idx & 63;
    float acc = b[d];
#pragma unroll
    for (int i = 0; i < NODE_IN; i++) acc += nf[n * NODE_IN + i] * W[i * 64 + d];
    g_h[idx] = fmaxf(acc, 0.f);
    g_agg[idx] = cb[d];
}

// ---------------- edge hidden (fp16 out): h = relu(edge_feat @ W1 + b1) ----------------
__global__ void k_edgehid(const float* __restrict__ ef, const float* __restrict__ W1,
                          const float* __restrict__ b1) {
    int idx = blockIdx.x * 256 + threadIdx.x;   // exactly N_EDGES*128
    int e = idx >> 7, k = idx & 127;
    float acc = b1[k];
#pragma unroll
    for (int i = 0; i < EDGE_IN; i++) acc += ef[e * EDGE_IN + i] * W1[i * EHID + k];
    g_hedge16[idx] = __float2half(fmaxf(acc, 0.f));
}

// ---------------- big GEMM via HMMA: block 128x256, warp 64x64, cp.async 2-stage --------
#define BM 128
#define BN 256
#define BK 32
__global__ __launch_bounds__(256) void k_gemm(const float* __restrict__ b2) {
    __shared__ __half As[2][BM * BK];   // 2 x 8 KB, chunk-swizzled (4 chunks/row)
    __shared__ __half Bs[2][BK * BN];   // 2 x 16 KB, chunk-swizzled (32 chunks/row)
    const int tid = threadIdx.x;
    const int wid = tid >> 5, lane = tid & 31;
    const int warp_m = wid & 1, warp_n = wid >> 1;   // 2 x 4 warps
    const int e0 = blockIdx.y * BM;
    const int j0 = blockIdx.x * BN;
    const int li = lane & 7, grp = lane >> 3;
    const unsigned As_b = sm_u32(As), Bs_b = sm_u32(Bs);

    const int a_row0 = tid >> 2, a_ck = tid & 3;     // + 64 rows for second A chunk
    const int b_row0 = tid >> 5, b_ck = tid & 31;    // + 8,16,24 rows for B chunks

    float acc[4][8][4];
#pragma unroll
    for (int f = 0; f < 4; f++)
#pragma unroll
        for (int j = 0; j < 8; j++)
#pragma unroll
            for (int q = 0; q < 4; q++) acc[f][j][q] = 0.f;

#define ISSUE_STAGE(kb, st) do {                                                   \
    _Pragma("unroll")                                                              \
    for (int l = 0; l < 2; l++) {                                                  \
        int row = a_row0 + l * 64;                                                 \
        int e = e0 + row;                                                          \
        unsigned dsta = As_b + (st) * 8192 +                                       \
            (((row << 2) + (a_ck ^ (row & 3))) * 16);                              \
        cp16(dsta, g_hedge16 + (size_t)e * 128 + (kb) * 32 + a_ck * 8,             \
             (e < N_EDGES) ? 16 : 0);                                              \
    }                                                                              \
    _Pragma("unroll")                                                              \
    for (int l = 0; l < 4; l++) {                                                  \
        int row = b_row0 + l * 8;                                                  \
        int cks = (b_ck & 24) | ((b_ck & 7) ^ (row & 7));                          \
        unsigned dstb = Bs_b + (st) * 16384 + (((row << 5) + cks) * 16);           \
        cp16(dstb, g_W2h + (size_t)((kb) * 32 + row) * 4096 + j0 + b_ck * 8, 16);  \
    }                                                                              \
    CP_COMMIT();                                                                   \
} while (0)

    ISSUE_STAGE(0, 0);
#pragma unroll
    for (int kb = 0; kb < 4; kb++) {
        if (kb < 3) { ISSUE_STAGE(kb + 1, (kb + 1) & 1); CP_WAIT(1); }
        else        { CP_WAIT(0); }
        __syncthreads();
        const unsigned Abase = As_b + (kb & 1) * 8192;
        const unsigned Bbase = Bs_b + (kb & 1) * 16384;
#pragma unroll
        for (int s = 0; s < 2; s++) {
            unsigned a[4][4];
#pragma unroll
            for (int f = 0; f < 4; f++) {
                int m0 = warp_m * 64 + f * 16;
                int row = m0 + li + (grp & 1) * 8;
                int ck = (s * 2 + (grp >> 1)) ^ (row & 3);
                LDSM4(a[f][0], a[f][1], a[f][2], a[f][3],
                      Abase + ((row << 2) + ck) * 16);
            }
            unsigned b[4][4];
#pragma unroll
            for (int p = 0; p < 4; p++) {
                int row = s * 16 + li + (grp & 1) * 8;
                int c = warp_n * 8 + p * 2 + (grp >> 1);
                int cks = (c & 24) | ((c & 7) ^ (row & 7));
                LDSM4T(b[p][0], b[p][1], b[p][2], b[p][3],
                       Bbase + ((row << 5) + cks) * 16);
            }
#pragma unroll
            for (int f = 0; f < 4; f++)
#pragma unroll
                for (int p = 0; p < 4; p++) {
                    MMA16816(acc[f][p * 2],     a[f], b[p][0], b[p][1]);
                    MMA16816(acc[f][p * 2 + 1], a[f], b[p][2], b[p][3]);
                }
        }
        __syncthreads();
    }
    // epilogue: + bias, fp16, 4B coalesced stores
#pragma unroll
    for (int j = 0; j < 8; j++) {
        int cn = warp_n * 64 + j * 8 + (lane & 3) * 2;
        float bv0 = b2[j0 + cn], bv1 = b2[j0 + cn + 1];
#pragma unroll
        for (int f = 0; f < 4; f++) {
            int r = warp_m * 64 + f * 16 + (lane >> 2);
            int e = e0 + r;
            if (e < N_EDGES) {
                __half2 h = __floats2half2_rn(acc[f][j][0] + bv0, acc[f][j][1] + bv1);
                *(__half2*)(g_We16 + (size_t)e * 4096 + j0 + cn) = h;
            }
            if (e + 8 < N_EDGES) {
                __half2 h = __floats2half2_rn(acc[f][j][2] + bv0, acc[f][j][3] + bv1);
                *(__half2*)(g_We16 + (size_t)(e + 8) * 4096 + j0 + cn) = h;
            }
        }
    }
}

// ---------------- einsum + scatter: warp per edge, streaming uint4 loads ---------------
__global__ void k_einsum(const int* __restrict__ src, const int* __restrict__ dst) {
    __shared__ float xs[8][64];
    int w = threadIdx.x >> 5, t = threadIdx.x & 31;
    int e = (blockIdx.x << 3) + w;              // exactly N_EDGES
    int s = src[e];
    int j2 = t << 1;
    float2 v = *(const float2*)(g_h + s * 64 + j2);
    xs[w][j2] = v.x; xs[w][j2 + 1] = v.y;
    __syncwarp();
    const uint4* __restrict__ W4 = (const uint4*)(g_We16 + (size_t)e * 4096);
    const int cg = t & 7, rg = t >> 3;
    float acc[8];
#pragma unroll
    for (int k = 0; k < 8; k++) acc[k] = 0.f;
#pragma unroll
    for (int i = 0; i < 16; i++) {
        int r = i * 4 + rg;
        uint4 q = __ldcs(W4 + r * 8 + cg);
        float xi = xs[w][r];
        float2 f0 = __half22float2(*(__half2*)&q.x);
        float2 f1 = __half22float2(*(__half2*)&q.y);
        float2 f2 = __half22float2(*(__half2*)&q.z);
        float2 f3 = __half22float2(*(__half2*)&q.w);
        acc[0] = fmaf(xi, f0.x, acc[0]); acc[1] = fmaf(xi, f0.y, acc[1]);
        acc[2] = fmaf(xi, f1.x, acc[2]); acc[3] = fmaf(xi, f1.y, acc[3]);
        acc[4] = fmaf(xi, f2.x, acc[4]); acc[5] = fmaf(xi, f2.y, acc[5]);
        acc[6] = fmaf(xi, f3.x, acc[6]); acc[7] = fmaf(xi, f3.y, acc[7]);
    }
#pragma unroll
    for (int k = 0; k < 8; k++) {
        acc[k] += __shfl_xor_sync(0xffffffffu, acc[k], 8);
        acc[k] += __shfl_xor_sync(0xffffffffu, acc[k], 16);
    }
    int dn = dst[e];
    int k0 = rg * 2;
    int col = cg * 8 + k0;
    atomicAdd(g_agg + dn * 64 + col,     acc[k0]);
    atomicAdd(g_agg + dn * 64 + col + 1, acc[k0 + 1]);
}

// ---------------- GRU cell: smem-cached fp16 weights, 8 warps/block, shfl broadcast -----
__global__ __launch_bounds__(256) void k_gru(const float* __restrict__ bih,
                                             const float* __restrict__ bhh,
                                             const float* __restrict__ cb) {
    __shared__ __half2 sW[64 * 96];   // 24 KB  Wih^T [64][192] as half2 pairs
    __shared__ __half2 sU[64 * 96];   // 24 KB  Whh^T
    const int tid = threadIdx.x;
    {
        const uint4* gw = (const uint4*)g_WihT16;
        const uint4* gu = (const uint4*)g_WhhT16;
        uint4* dw = (uint4*)sW;
        uint4* du = (uint4*)sU;
        for (int i = tid; i < 1536; i += 256) { dw[i] = gw[i]; du[i] = gu[i]; }
    }
    __syncthreads();
    const int w = tid >> 5, t = tid & 31;
    const int n = blockIdx.x * 8 + w;           // exactly N_NODES (grid 1250)
    const int j = t << 1;
    float2 av = *(const float2*)(g_agg + n * 64 + j);
    float2 x2; x2.x = fmaxf(av.x, 0.f); x2.y = fmaxf(av.y, 0.f);
    float2 hv = *(const float2*)(g_h + n * 64 + j);
    *(float2*)(g_agg + n * 64 + j) = *(const float2*)(cb + j);   // reset for next step

    float rx0 = 0.f, rx1 = 0.f, zx0 = 0.f, zx1 = 0.f, nx0 = 0.f, nx1 = 0.f;
    float rh0 = 0.f, rh1 = 0.f, zh0 = 0.f, zh1 = 0.f, nh0 = 0.f, nh1 = 0.f;
#pragma unroll
    for (int i = 0; i < 64; i++) {
        float xi = __shfl_sync(0xffffffffu, (i & 1) ? x2.y : x2.x, i >> 1);
        float hi = __shfl_sync(0xffffffffu, (i & 1) ? hv.y : hv.x, i >> 1);
        float2 wr = __half22float2(sW[i * 96 + t]);
        float2 wz = __half22float2(sW[i * 96 + 32 + t]);
        float2 wn = __half22float2(sW[i * 96 + 64 + t]);
        float2 ur = __half22float2(sU[i * 96 + t]);
        float2 uz = __half22float2(sU[i * 96 + 32 + t]);
        float2 un = __half22float2(sU[i * 96 + 64 + t]);
        rx0 = fmaf(xi, wr.x, rx0); rx1 = fmaf(xi, wr.y, rx1);
        zx0 = fmaf(xi, wz.x, zx0); zx1 = fmaf(xi, wz.y, zx1);
        nx0 = fmaf(xi, wn.x, nx0); nx1 = fmaf(xi, wn.y, nx1);
        rh0 = fmaf(hi, ur.x, rh0); rh1 = fmaf(hi, ur.y, rh1);
        zh0 = fmaf(hi, uz.x, zh0); zh1 = fmaf(hi, uz.y, zh1);
        nh0 = fmaf(hi, un.x, nh0); nh1 = fmaf(hi, un.y, nh1);
    }
    float r0 = sigf(rx0 + bih[j]         + rh0 + bhh[j]);
    float r1 = sigf(rx1 + bih[j + 1]     + rh1 + bhh[j + 1]);
    float z0 = sigf(zx0 + bih[64 + j]    + zh0 + bhh[64 + j]);
    float z1 = sigf(zx1 + bih[64 + j + 1]+ zh1 + bhh[64 + j + 1]);
    float n0 = tanhf(nx0 + bih[128 + j]     + r0 * (nh0 + bhh[128 + j]));
    float n1 = tanhf(nx1 + bih[128 + j + 1] + r1 * (nh1 + bhh[128 + j + 1]));
    float2 o;
    o.x = (1.f - z0) * n0 + z0 * hv.x;
    o.y = (1.f - z1) * n1 + z1 * hv.y;
    *(float2*)(g_h + n * 64 + j) = o;
}

// ---------------- fused Set2Set + head: one block per graph ----------------
__device__ __forceinline__ void lstm_layer(const __half* __restrict__ WT,
                                           const __half* __restrict__ UT,
                                           const float* __restrict__ bih,
                                           const float* __restrict__ bhh,
                                           const float* __restrict__ x, int in_dim,
                                           float* h, float* c, float* g, int tid) {
    float acc = bih[tid] + bhh[tid];
#pragma unroll 4
    for (int i = 0; i < in_dim; i++) acc += x[i] * __half2float(WT[i * 256 + tid]);
#pragma unroll 4
    for (int i = 0; i < 64; i++) acc += h[i] * __half2float(UT[i * 256 + tid]);
    g[tid] = acc;
    __syncthreads();
    if (tid < 64) {
        float ig = sigf(g[tid]);
        float fg = sigf(g[64 + tid]);
        float gg = tanhf(g[128 + tid]);
        float og = sigf(g[192 + tid]);
        float cc = fg * c[tid] + ig * gg;
        c[tid] = cc;
        h[tid] = og * tanhf(cc);
    }
    __syncthreads();
}

__global__ __launch_bounds__(256) void k_set2set(
        const int* __restrict__ gid,
        const float* __restrict__ l0_bih, const float* __restrict__ l0_bhh,
        const float* __restrict__ l12_bih, const float* __restrict__ l12_bhh,
        const float* __restrict__ lin1_W, const float* __restrict__ lin1_b,
        const float* __restrict__ lin2_W, const float* __restrict__ lin2_b,
        float* __restrict__ out) {
    __shared__ float gsh[256];
    __shared__ float hst[3][64], cst[3][64];
    __shared__ float qstar[128];
    __shared__ float m8[8], s8[8];
    __shared__ float r8[8][64];
    __shared__ float t1s[64];
    __shared__ int rng[2];

    const int b = blockIdx.x;
    const int tid = threadIdx.x;
    const int wid = tid >> 5, lane = tid & 31;

    if (tid == 0) {
        int lo = 0, hi = N_NODES;
        while (lo < hi) { int mid = (lo + hi) >> 1; if (gid[mid] < b) lo = mid + 1; else hi = mid; }
        rng[0] = lo;
        lo = 0; hi = N_NODES;
        while (lo < hi) { int mid = (lo + hi) >> 1; if (gid[mid] < b + 1) lo = mid + 1; else hi = mid; }
        rng[1] = lo;
    }
    if (tid < 128) qstar[tid] = 0.f;
    if (tid < 64) {
        hst[0][tid] = 0.f; hst[1][tid] = 0.f; hst[2][tid] = 0.f;
        cst[0][tid] = 0.f; cst[1][tid] = 0.f; cst[2][tid] = 0.f;
    }
    __syncthreads();
    const int ns = rng[0], ne = rng[1];

    for (int step = 0; step < S2S_STEPS; step++) {
        lstm_layer(g_L0ihT, g_L0hhT, l0_bih, l0_bhh, qstar, 128,
                   hst[0], cst[0], gsh, tid);
        lstm_layer(g_L12ihT, g_L12hhT, l12_bih, l12_bhh, hst[0], 64,
                   hst[1], cst[1], gsh, tid);
        lstm_layer(g_L12ihT + 16384, g_L12hhT + 16384, l12_bih + 256, l12_bhh + 256,
                   hst[1], 64, hst[2], cst[2], gsh, tid);
        // attention with streaming softmax; q = hst[2]
        float qa = hst[2][lane], qb = hst[2][32 + lane];
        float m = -INFINITY, ssum = 0.f, r0 = 0.f, r1 = 0.f;
        for (int n = ns + wid; n < ne; n += 8) {
            float o0 = g_h[n * 64 + lane];
            float o1 = g_h[n * 64 + 32 + lane];
            float part = o0 * qa + o1 * qb;
#pragma unroll
            for (int o = 16; o; o >>= 1) part += __shfl_xor_sync(0xffffffffu, part, o);
            if (part > m) {
                float sc = expf(m - part);
                ssum = ssum * sc + 1.f;
                r0 = r0 * sc + o0;
                r1 = r1 * sc + o1;
                m = part;
            } else {
                float wg = expf(part - m);
                ssum += wg;
                r0 += wg * o0;
                r1 += wg * o1;
            }
        }
        if (lane == 0) { m8[wid] = m; s8[wid] = ssum; }
        r8[wid][lane] = r0;
        r8[wid][32 + lane] = r1;
        __syncthreads();
        if (tid < 64) {
            float M = -INFINITY;
#pragma unroll
            for (int w = 0; w < 8; w++) if (s8[w] > 0.f) M = fmaxf(M, m8[w]);
            float S = 0.f, R = 0.f;
#pragma unroll
            for (int w = 0; w < 8; w++) {
                if (s8[w] > 0.f) {
                    float sc = expf(m8[w] - M);
                    S += s8[w] * sc;
                    R += r8[w][tid] * sc;
                }
            }
            qstar[tid] = hst[2][tid];
            qstar[64 + tid] = (S > 0.f) ? (R / S) : 0.f;
        }
        __syncthreads();
    }
    // head: t1 = relu(qstar @ lin1 + b1); out = t1 @ lin2 + b2
    if (tid < 64) {
        float acc = lin1_b[tid];
#pragma unroll 4
        for (int i = 0; i < 128; i++) acc += qstar[i] * lin1_W[i * 64 + tid];
        t1s[tid] = fmaxf(acc, 0.f);
    }
    __syncthreads();
    if (tid < OUT_DIM) {
        float acc = lin2_b[tid];
#pragma unroll 4
        for (int d = 0; d < 64; d++) acc += t1s[d] * lin2_W[d * OUT_DIM + tid];
        out[b * OUT_DIM + tid] = acc;
    }
}

// ---------------- launcher ----------------
extern "C" void kernel_launch(void* const* d_in, const int* in_sizes, int n_in,
                              void* d_out, int out_size) {
    const float* node_feat = (const float*)d_in[0];
    const float* edge_feat = (const float*)d_in[1];
    const int*   src       = (const int*)d_in[2];
    const int*   dst       = (const int*)d_in[3];
    const int*   gid       = (const int*)d_in[4];
    // d_in[5] = num_graphs (unused; B fixed)
    const float* lin0_W = (const float*)d_in[6];
    const float* lin0_b = (const float*)d_in[7];
    const float* em_W1  = (const float*)d_in[8];
    const float* em_b1  = (const float*)d_in[9];
    const float* em_W2  = (const float*)d_in[10];
    const float* em_b2  = (const float*)d_in[11];
    const float* conv_bias = (const float*)d_in[12];
    const float* gru_Wih = (const float*)d_in[13];
    const float* gru_Whh = (const float*)d_in[14];
    const float* gru_bih = (const float*)d_in[15];
    const float* gru_bhh = (const float*)d_in[16];
    const float* l0_Wih = (const float*)d_in[17];
    const float* l0_Whh = (const float*)d_in[18];
    const float* l0_bih = (const float*)d_in[19];
    const float* l0_bhh = (const float*)d_in[20];
    const float* l12_Wih = (const float*)d_in[21];
    const float* l12_Whh = (const float*)d_in[22];
    const float* l12_bih = (const float*)d_in[23];
    const float* l12_bhh = (const float*)d_in[24];
    const float* lin1_W = (const float*)d_in[25];
    const float* lin1_b = (const float*)d_in[26];
    const float* lin2_W = (const float*)d_in[27];
    const float* lin2_b = (const float*)d_in[28];
    float* out = (float*)d_out;

    (void)in_sizes; (void)n_in; (void)out_size;

    k_prep<<<128, 256>>>(gru_Wih, gru_Whh, l0_Wih, l0_Whh, l12_Wih, l12_Whh, em_W2);
    k_lin0<<<(N_NODES * 64) / 256, 256>>>(node_feat, lin0_W, lin0_b, conv_bias);
    k_edgehid<<<(N_EDGES * EHID) / 256, 256>>>(edge_feat, em_W1, em_b1);
    k_gemm<<<dim3(DDIM / BN, (N_EDGES + BM - 1) / BM), 256>>>(em_b2);

    for (int s = 0; s < MP_STEPS; s++) {
        k_einsum<<<N_EDGES / 8, 256>>>(src, dst);
        k_gru<<<N_NODES / 8, 256>>>(gru_bih, gru_bhh, conv_bias);
    }

    k_set2set<<<NB, 256>>>(gid, l0_bih, l0_bhh, l12_bih, l12_bhh,
                           lin1_W, lin1_b, lin2_W, lin2_b, out);
}